// round 14
// baseline (speedup 1.0000x reference)
#include <cuda_runtime.h>
#include <cuda_bf16.h>
#include <math.h>
#include <stdint.h>

// Problem constants
#define Bsz 1024
#define Tsz 128
#define Fsz 9
#define Hsz 256
#define Psz 2048
#define NHEADS 4
#define DHEAD 64
#define BT (Bsz*Tsz)
#define NCTA 128
#define PH (Psz*Hsz)

// ---------------- scratch (static device globals; no allocation) ----------------
__device__ float g_h[BT * Hsz];        // VSN out / LSTM hseq (tf32-rounded at write)
__device__ float g_xp[BT * 4 * Hsz];   // xp precompute / kv buffer (full fp32)
__device__ float g_q[Bsz * Hsz];       // q projection out
__device__ float g_qg[Bsz * Hsz];      // gathered h_last (tf32-valued)
__device__ float g_o[Bsz * Hsz];       // attention out (tf32-rounded)
__device__ float g_hidden[Bsz * Hsz];  // (tf32-rounded via roundC)
__device__ float g_peT[Hsz * Psz];     // transposed product embeds [h][p]
__device__ float g_degs[Psz];
__device__ float g_agg[Psz * Hsz];     // (tf32-rounded in reduce)
__device__ float g_trans[Psz * Hsz];
__device__ float g_cat[Bsz * 512];     // [hidden | rounded enriched]
__device__ float g_gatep[Bsz * Hsz];   // gate preactivation
__device__ float g_wr[983040];         // rounded weights
__device__ float g_adjr[Psz * Psz];    // rounded adj
__device__ float g_part[4 * PH];       // split-K partials for adj GEMM

// per-group barrier counters (16 groups; monotonic, separate cache lines)
__device__ unsigned g_grp_cnt[16 * 32];

__device__ __forceinline__ float sigmoidf_(float x) { return 1.0f / (1.0f + expf(-x)); }
// fast (MUFU-based) versions — exact formulas, ~1e-6 rel error, saturate correctly
__device__ __forceinline__ float fsig(float x) {
    return __fdividef(1.0f, 1.0f + __expf(-x));
}
__device__ __forceinline__ float ftanh_(float x) {
    return 1.0f - __fdividef(2.0f, __expf(2.0f * x) + 1.0f);
}

// ---------------- helpers (target-independent PTX) ----------------
__device__ __forceinline__ uint32_t f2tf32(float f) {
    uint32_t r;
    asm("cvt.rna.tf32.f32 %0, %1;" : "=r"(r) : "f"(f));
    return r;
}
__device__ __forceinline__ float rnd_tf32(float f) { return __uint_as_float(f2tf32(f)); }
__device__ __forceinline__ void mma_m16n8k8(float d[4], const uint32_t a[4], const uint32_t b[2]) {
    asm volatile(
        "mma.sync.aligned.m16n8k8.row.col.f32.tf32.tf32.f32 "
        "{%0,%1,%2,%3}, {%4,%5,%6,%7}, {%8,%9}, {%0,%1,%2,%3};"
        : "+f"(d[0]), "+f"(d[1]), "+f"(d[2]), "+f"(d[3])
        : "r"(a[0]), "r"(a[1]), "r"(a[2]), "r"(a[3]), "r"(b[0]), "r"(b[1]));
}
__device__ __forceinline__ uint32_t smem_u32(const void* p) {
    uint32_t a;
    asm("{ .reg .u64 t; cvta.to.shared.u64 t, %1; cvt.u32.u64 %0, t; }" : "=r"(a) : "l"(p));
    return a;
}
__device__ __forceinline__ void ldsm_x4(uint32_t r[4], uint32_t addr) {
    asm volatile("ldmatrix.sync.aligned.m8n8.x4.shared.b16 {%0,%1,%2,%3}, [%4];"
                 : "=r"(r[0]), "=r"(r[1]), "=r"(r[2]), "=r"(r[3]) : "r"(addr));
}
__device__ __forceinline__ void ldsm_x2(uint32_t r[2], uint32_t addr) {
    asm volatile("ldmatrix.sync.aligned.m8n8.x2.shared.b16 {%0,%1}, [%2];"
                 : "=r"(r[0]), "=r"(r[1]) : "r"(addr));
}
__device__ __forceinline__ void cp_async16(uint32_t dst, const void* src) {
    asm volatile("cp.async.cg.shared.global [%0], [%1], 16;" :: "r"(dst), "l"(src));
}
__device__ __forceinline__ void cp_commit() {
    asm volatile("cp.async.commit_group;" ::: "memory");
}
template<int N> __device__ __forceinline__ void cp_wait() {
    asm volatile("cp.async.wait_group %0;" :: "n"(N) : "memory");
}

// ---------------- round_all: fused RNE rounding of all 7 weight blobs ----------------
// float4 segment offsets: 0|65536|131072|163840|180224|196608|212992|245760
__global__ __launch_bounds__(256) void round_all(
    const float* __restrict__ s0, const float* __restrict__ s1,
    const float* __restrict__ s2, const float* __restrict__ s3,
    const float* __restrict__ s4, const float* __restrict__ s5,
    const float* __restrict__ s6, float* __restrict__ dst)
{
    int i = blockIdx.x * 256 + threadIdx.x;
    if (i >= 245760) return;
    const float* src; int off;
    if      (i < 65536)  { src = s0; off = 0; }
    else if (i < 131072) { src = s1; off = 65536; }
    else if (i < 163840) { src = s2; off = 131072; }
    else if (i < 180224) { src = s3; off = 163840; }
    else if (i < 196608) { src = s4; off = 180224; }
    else if (i < 212992) { src = s5; off = 196608; }
    else                 { src = s6; off = 212992; }
    float4 v = ((const float4*)src)[i - off];
    v.x = rnd_tf32(v.x); v.y = rnd_tf32(v.y); v.z = rnd_tf32(v.z); v.w = rnd_tf32(v.w);
    ((float4*)dst)[i] = v;
}

// ================= persistent LSTM layer =================
__global__ __launch_bounds__(256) void lstm_persist(
    const float* __restrict__ xp, float* __restrict__ hseq,
    const float* __restrict__ Whh)
{
    extern __shared__ char sbuf[];
    uint32_t (*As)[260] = (uint32_t(*)[260])sbuf;
    uint32_t (*Bs)[260] = (uint32_t(*)[260])(sbuf + 66560);
    float (*Cs)[132]    = (float(*)[132])sbuf;   // aliases As

    const int tid = threadIdx.x;
    const int wid = tid >> 5, lane = tid & 31;
    const int wr = wid & 1, wc = wid >> 1;
    const int grp = blockIdx.x >> 3;
    const int m0 = grp * 64;
    const int j0 = (blockIdx.x & 7) * 32;
    unsigned* cntP = &g_grp_cnt[grp * 32];

    const uint32_t asBase = smem_u32(&As[0][0]);
    const uint32_t bsBase = smem_u32(&Bs[0][0]);

    for (int i = tid; i < 128 * 64; i += 256) {
        int r = i >> 6, cc = (i & 63) << 2;
        int wrow = (r >> 5) * 256 + j0 + (r & 31);
        float4 v = *(const float4*)&Whh[(size_t)wrow * 256 + cc];
        uint32_t* p = &Bs[r][cc];
        p[0] = f2tf32(v.x); p[1] = f2tf32(v.y); p[2] = f2tf32(v.z); p[3] = f2tf32(v.w);
    }

    const int lg = lane >> 3, lr8 = lane & 7;
    uint32_t aAddr[2], bAddr[4];
    #pragma unroll
    for (int mi = 0; mi < 2; mi++)
        aAddr[mi] = asBase + (uint32_t)(wr * 32 + mi * 16 + lr8 + (lg & 1) * 8) * 1040u
                    + (uint32_t)((lg >> 1) * 4) * 4u;
    #pragma unroll
    for (int ni = 0; ni < 4; ni++)
        bAddr[ni] = bsBase + (uint32_t)(wc * 32 + ni * 8 + lr8) * 1040u
                    + (uint32_t)((lg & 1) * 4) * 4u;

    const int srow = tid >> 2, sc0 = tid & 3;
    const uint32_t sdst0 = asBase + (uint32_t)srow * 1040u;

    const int bl = tid >> 2, jl0 = (tid & 3) * 8;
    const int b = m0 + bl;
    float creg[8];
    unsigned base = 0;

    // ---- t = 0 ----
    {
        const float* xb = &xp[((size_t)b * Tsz + 0) * 1024 + j0 + jl0];
        float xi[8], xg[8], xo[8], hn[8];
        *(float4*)&xi[0] = *(const float4*)&xb[0];    *(float4*)&xi[4] = *(const float4*)&xb[4];
        *(float4*)&xg[0] = *(const float4*)&xb[512];  *(float4*)&xg[4] = *(const float4*)&xb[516];
        *(float4*)&xo[0] = *(const float4*)&xb[768];  *(float4*)&xo[4] = *(const float4*)&xb[772];
        #pragma unroll
        for (int e = 0; e < 8; e++) {
            creg[e] = fsig(xi[e]) * ftanh_(xg[e]);
            hn[e] = rnd_tf32(fsig(xo[e]) * ftanh_(creg[e]));
        }
        float* hb = &hseq[((size_t)b * Tsz + 0) * 256 + j0 + jl0];
        *(float4*)&hb[0] = *(float4*)&hn[0];  *(float4*)&hb[4] = *(float4*)&hn[4];
    }
    __syncthreads();
    if (tid == 0) {
        unsigned arr;
        asm volatile("atom.release.gpu.add.u32 %0, [%1], 1;" : "=r"(arr) : "l"(cntP) : "memory");
        base = arr & ~7u;
    }

    for (int t = 1; t < Tsz; t++) {
        // prefetch xp (overlaps inter-CTA wait)
        const float* xb = &xp[((size_t)b * Tsz + t) * 1024 + j0 + jl0];
        float xi[8], xf[8], xg[8], xo[8];
        *(float4*)&xi[0] = *(const float4*)&xb[0];    *(float4*)&xi[4] = *(const float4*)&xb[4];
        *(float4*)&xf[0] = *(const float4*)&xb[256];  *(float4*)&xf[4] = *(const float4*)&xb[260];
        *(float4*)&xg[0] = *(const float4*)&xb[512];  *(float4*)&xg[4] = *(const float4*)&xb[516];
        *(float4*)&xo[0] = *(const float4*)&xb[768];  *(float4*)&xo[4] = *(const float4*)&xb[772];

        if (tid == 0) {
            unsigned target = base + 8u * (unsigned)t;
            unsigned c;
            do {
                asm volatile("ld.acquire.gpu.u32 %0, [%1];" : "=r"(c) : "l"(cntP) : "memory");
            } while ((int)(c - target) < 0);
        }
        __syncthreads();

        {
            const float* srcrow = &hseq[((size_t)(m0 + srow) * Tsz + (t - 1)) * 256];
            #pragma unroll
            for (int u = 0; u < 8; u++) {
                int cf4 = sc0 + u * 4;
                cp_async16(sdst0 + (uint32_t)cf4 * 16u, srcrow + cf4 * 4);
            }
            cp_commit();
            #pragma unroll
            for (int u = 8; u < 16; u++) {
                int cf4 = sc0 + u * 4;
                cp_async16(sdst0 + (uint32_t)cf4 * 16u, srcrow + cf4 * 4);
            }
            cp_commit();
        }

        float d[2][4][4] = {};
        cp_wait<1>();
        __syncthreads();
        #pragma unroll 8
        for (int k8 = 0; k8 < 16; k8++) {
            const uint32_t off = (uint32_t)k8 * 32u;
            uint32_t a[2][4], bfr[4][2];
            #pragma unroll
            for (int mi = 0; mi < 2; mi++) ldsm_x4(a[mi], aAddr[mi] + off);
            #pragma unroll
            for (int ni = 0; ni < 4; ni++) ldsm_x2(bfr[ni], bAddr[ni] + off);
            #pragma unroll
            for (int mi = 0; mi < 2; mi++)
                #pragma unroll
                for (int ni = 0; ni < 4; ni++)
                    mma_m16n8k8(d[mi][ni], a[mi], bfr[ni]);
        }
        cp_wait<0>();
        __syncthreads();
        #pragma unroll 8
        for (int k8 = 16; k8 < 32; k8++) {
            const uint32_t off = (uint32_t)k8 * 32u;
            uint32_t a[2][4], bfr[4][2];
            #pragma unroll
            for (int mi = 0; mi < 2; mi++) ldsm_x4(a[mi], aAddr[mi] + off);
            #pragma unroll
            for (int ni = 0; ni < 4; ni++) ldsm_x2(bfr[ni], bAddr[ni] + off);
            #pragma unroll
            for (int mi = 0; mi < 2; mi++)
                #pragma unroll
                for (int ni = 0; ni < 4; ni++)
                    mma_m16n8k8(d[mi][ni], a[mi], bfr[ni]);
        }
        __syncthreads();

        const int gID = lane >> 2, tig = lane & 3;
        #pragma unroll
        for (int mi = 0; mi < 2; mi++) {
            int m = wr * 32 + mi * 16 + gID;
            #pragma unroll
            for (int ni = 0; ni < 4; ni++) {
                int n = wc * 32 + ni * 8 + tig * 2;
                *(float2*)&Cs[m][n]     = make_float2(d[mi][ni][0], d[mi][ni][1]);
                *(float2*)&Cs[m + 8][n] = make_float2(d[mi][ni][2], d[mi][ni][3]);
            }
        }
        __syncthreads();

        // fused cell update: vectorized Cs reads (row stride 528 B, 16B-aligned)
        float gi[8], gf[8], gg[8], go[8], hn[8];
        *(float4*)&gi[0] = *(const float4*)&Cs[bl][jl0];
        *(float4*)&gi[4] = *(const float4*)&Cs[bl][jl0 + 4];
        *(float4*)&gf[0] = *(const float4*)&Cs[bl][32 + jl0];
        *(float4*)&gf[4] = *(const float4*)&Cs[bl][32 + jl0 + 4];
        *(float4*)&gg[0] = *(const float4*)&Cs[bl][64 + jl0];
        *(float4*)&gg[4] = *(const float4*)&Cs[bl][64 + jl0 + 4];
        *(float4*)&go[0] = *(const float4*)&Cs[bl][96 + jl0];
        *(float4*)&go[4] = *(const float4*)&Cs[bl][96 + jl0 + 4];
        #pragma unroll
        for (int e = 0; e < 8; e++) {
            float vi = gi[e] + xi[e];
            float vf = gf[e] + xf[e];
            float vg = gg[e] + xg[e];
            float vo = go[e] + xo[e];
            creg[e] = fsig(vf) * creg[e] + fsig(vi) * ftanh_(vg);
            hn[e] = rnd_tf32(fsig(vo) * ftanh_(creg[e]));
        }
        float* hb = &hseq[((size_t)b * Tsz + t) * 256 + j0 + jl0];
        *(float4*)&hb[0] = *(float4*)&hn[0];  *(float4*)&hb[4] = *(float4*)&hn[4];

        __syncthreads();
        if (tid == 0)
            asm volatile("red.release.gpu.add.u32 [%0], 1;" :: "l"(cntP) : "memory");
    }
}

// ================= mm_nt_tf32 v2: cp.async double-buffered, CTA 128x128, split-K =================
__global__ __launch_bounds__(256) void mm_nt_tf32(
    const float* __restrict__ A, const float* __restrict__ W,
    const float* __restrict__ b1, const float* __restrict__ b2,
    const float* __restrict__ rs,
    float* __restrict__ C, int Nall, int lda, int Kchunk, int roundC, size_t partStride)
{
    extern __shared__ char mmbuf[];
    const uint32_t sb = smem_u32(mmbuf);
    const int tid = threadIdx.x;
    const int wid = tid >> 5, lane = tid & 31;
    const int gID = lane >> 2, tig = lane & 3;
    const int wr = wid & 3, wc = wid >> 2;
    const int m0 = blockIdx.y * 128, n0 = blockIdx.x * 128;
    const int kStart = blockIdx.z * Kchunk;
    C += (size_t)blockIdx.z * partStride;

    const int lg = lane >> 3, lr8 = lane & 7;
    uint32_t aOff[2], bOff[4];
    #pragma unroll
    for (int mi = 0; mi < 2; mi++)
        aOff[mi] = (uint32_t)(wr * 32 + mi * 16 + lr8 + (lg & 1) * 8) * 144u
                   + (uint32_t)((lg >> 1) * 4) * 4u;
    #pragma unroll
    for (int ni = 0; ni < 4; ni++)
        bOff[ni] = 18432u + (uint32_t)(wc * 64 + ni * 16 + (lg >> 1) * 8 + lr8) * 144u
                   + (uint32_t)((lg & 1) * 4) * 4u;

    float d[2][8][4] = {};
    const int nk = Kchunk >> 5;

    auto load_stage = [&](int kc, int s) {
        const int k0 = kStart + (kc << 5);
        const uint32_t base = sb + (uint32_t)s * 36864u;
        #pragma unroll
        for (int i = 0; i < 4; i++) {
            int idx = tid + i * 256;
            int r = idx >> 3, c16 = idx & 7;
            cp_async16(base + (uint32_t)r * 144u + (uint32_t)c16 * 16u,
                       &A[(size_t)(m0 + r) * lda + k0 + c16 * 4]);
        }
        #pragma unroll
        for (int i = 0; i < 4; i++) {
            int idx = tid + i * 256;
            int r = idx >> 3, c16 = idx & 7;
            cp_async16(base + 18432u + (uint32_t)r * 144u + (uint32_t)c16 * 16u,
                       &W[(size_t)(n0 + r) * lda + k0 + c16 * 4]);
        }
        cp_commit();
    };

    load_stage(0, 0);
    for (int kc = 0; kc < nk; kc++) {
        const int s = kc & 1;
        const uint32_t stBase = sb + (uint32_t)s * 36864u;
        if (kc + 1 < nk) {
            load_stage(kc + 1, s ^ 1);
            cp_wait<1>();
        } else {
            cp_wait<0>();
        }
        __syncthreads();
        #pragma unroll
        for (int k8 = 0; k8 < 4; k8++) {
            const uint32_t off = stBase + (uint32_t)k8 * 32u;
            uint32_t a[2][4], b[4][4];
            #pragma unroll
            for (int mi = 0; mi < 2; mi++) ldsm_x4(a[mi], off + aOff[mi]);
            #pragma unroll
            for (int ni = 0; ni < 4; ni++) ldsm_x4(b[ni], off + bOff[ni]);
            #pragma unroll
            for (int mi = 0; mi < 2; mi++)
                #pragma unroll
                for (int ni = 0; ni < 4; ni++) {
                    mma_m16n8k8(d[mi][ni * 2],     a[mi], &b[ni][0]);
                    mma_m16n8k8(d[mi][ni * 2 + 1], a[mi], &b[ni][2]);
                }
        }
        __syncthreads();
    }
    #pragma unroll
    for (int mi = 0; mi < 2; mi++) {
        int m = m0 + wr * 32 + mi * 16 + gID;
        float s0 = rs ? rs[m] : 1.0f;
        float s1 = rs ? rs[m + 8] : 1.0f;
        #pragma unroll
        for (int ni = 0; ni < 8; ni++) {
            int n = n0 + wc * 64 + ni * 8 + tig * 2;
            float bb0 = 0.f, bb1 = 0.f;
            if (b1) { bb0 += b1[n]; bb1 += b1[n + 1]; }
            if (b2) { bb0 += b2[n]; bb1 += b2[n + 1]; }
            float v00 = d[mi][ni][0] * s0 + bb0;
            float v01 = d[mi][ni][1] * s0 + bb1;
            float v10 = d[mi][ni][2] * s1 + bb0;
            float v11 = d[mi][ni][3] * s1 + bb1;
            if (roundC) { v00 = rnd_tf32(v00); v01 = rnd_tf32(v01);
                          v10 = rnd_tf32(v10); v11 = rnd_tf32(v11); }
            C[(size_t)m * Nall + n]           = v00;
            C[(size_t)m * Nall + n + 1]       = v01;
            C[(size_t)(m + 8) * Nall + n]     = v10;
            C[(size_t)(m + 8) * Nall + n + 1] = v11;
        }
    }
}

// ---------------- reduce split-K partials -> agg ----------------
__global__ __launch_bounds__(256) void agg_reduce(
    const float* __restrict__ part, const float* __restrict__ degscale,
    float* __restrict__ agg)
{
    int p = blockIdx.x, h = threadIdx.x;
    size_t i = (size_t)p * Hsz + h;
    float s = part[i] + part[i + PH] + part[i + 2 * (size_t)PH] + part[i + 3 * (size_t)PH];
    agg[i] = rnd_tf32(s * degscale[p]);
}

// ---------------- VSN: one warp per (b,t); outputs tf32-rounded ----------------
__global__ __launch_bounds__(256) void vsn_kernel(
    const float* __restrict__ x,
    const float* __restrict__ emb_w, const float* __restrict__ emb_b,
    const float* __restrict__ sel_w, const float* __restrict__ sel_b,
    float* __restrict__ h)
{
    const int lane = threadIdx.x & 31;
    const size_t bt = (size_t)blockIdx.x * 8 + (threadIdx.x >> 5);
    float xv = (lane < Fsz) ? x[bt * Fsz + lane] : 0.f;
    float xs[Fsz];
    #pragma unroll
    for (int f = 0; f < Fsz; f++) xs[f] = __shfl_sync(0xffffffffu, xv, f);
    float lg = -1e30f;
    if (lane < Fsz) {
        lg = sel_b[lane];
        #pragma unroll
        for (int j = 0; j < Fsz; j++) lg += xs[j] * sel_w[lane * Fsz + j];
    }
    float mx = lg;
    #pragma unroll
    for (int off = 16; off; off >>= 1) mx = fmaxf(mx, __shfl_xor_sync(0xffffffffu, mx, off));
    float ex = (lane < Fsz) ? expf(lg - mx) : 0.f;
    float den = ex;
    #pragma unroll
    for (int off = 16; off; off >>= 1) den += __shfl_xor_sync(0xffffffffu, den, off);
    float wv = ex / den;
    float wf[Fsz];
    #pragma unroll
    for (int f = 0; f < Fsz; f++) wf[f] = __shfl_sync(0xffffffffu, wv, f);

    const int o0 = lane * 8;
    float acc[8] = {};
    #pragma unroll
    for (int f = 0; f < Fsz; f++) {
        float4 w0 = *(const float4*)&emb_w[f * Hsz + o0];
        float4 w1 = *(const float4*)&emb_w[f * Hsz + o0 + 4];
        float4 c0 = *(const float4*)&emb_b[f * Hsz + o0];
        float4 c1 = *(const float4*)&emb_b[f * Hsz + o0 + 4];
        float wfx = wf[f], xf = xs[f];
        acc[0] += wfx * (xf * w0.x + c0.x); acc[1] += wfx * (xf * w0.y + c0.y);
        acc[2] += wfx * (xf * w0.z + c0.z); acc[3] += wfx * (xf * w0.w + c0.w);
        acc[4] += wfx * (xf * w1.x + c1.x); acc[5] += wfx * (xf * w1.y + c1.y);
        acc[6] += wfx * (xf * w1.z + c1.z); acc[7] += wfx * (xf * w1.w + c1.w);
    }
    #pragma unroll
    for (int e = 0; e < 8; e++) acc[e] = rnd_tf32(acc[e]);
    float* hb = &h[bt * Hsz + o0];
    *(float4*)&hb[0] = *(float4*)&acc[0];
    *(float4*)&hb[4] = *(float4*)&acc[4];
}

// ---------------- gather h_last ----------------
__global__ __launch_bounds__(256) void qgather_kernel(
    const float* __restrict__ h, float* __restrict__ qg)
{
    int b = blockIdx.x, tid = threadIdx.x;
    qg[(size_t)b * Hsz + tid] = h[((size_t)b * Tsz + (Tsz - 1)) * Hsz + tid];
}

// ---------------- attention (last query only); v-sum parallel over 128 threads ----------------
__global__ __launch_bounds__(128) void attn_last_kernel(
    const float* __restrict__ q, const float* __restrict__ kv,
    float* __restrict__ o)
{
    int b = blockIdx.x, hd = blockIdx.y;
    int tid = threadIdx.x;
    __shared__ float qs[DHEAD];
    __shared__ float sc[Tsz];
    __shared__ float red[Tsz];
    if (tid < DHEAD) qs[tid] = q[(size_t)b * Hsz + hd * DHEAD + tid];
    __syncthreads();
    const float* kp = &kv[((size_t)b * Tsz + tid) * 512 + hd * DHEAD];
    float s = 0.f;
#pragma unroll 8
    for (int d = 0; d < DHEAD; d++) s += qs[d] * kp[d];
    s *= 0.125f;
    sc[tid] = s;
    red[tid] = s;
    __syncthreads();
    for (int off = 64; off; off >>= 1) {
        if (tid < off) red[tid] = fmaxf(red[tid], red[tid + off]);
        __syncthreads();
    }
    float mx = red[0];
    __syncthreads();
    float e = expf(sc[tid] - mx);
    sc[tid] = e;
    red[tid] = e;
    __syncthreads();
    for (int off = 64; off; off >>= 1) {
        if (tid < off) red[tid] += red[tid + off];
        __syncthreads();
    }
    float inv = 1.0f / red[0];
    __syncthreads();
    sc[tid] *= inv;
    __syncthreads();
    // v-weighted sum: 128 threads, (d, half) split, then pairwise add
    {
        int dd = tid & 63, hf = tid >> 6;
        float acc = 0.f;
        const float* vbase = &kv[((size_t)b * Tsz + hf * 64) * 512 + 256 + hd * DHEAD + dd];
        #pragma unroll 8
        for (int t = 0; t < 64; t++)
            acc += sc[hf * 64 + t] * vbase[(size_t)t * 512];
        red[tid] = acc;
        __syncthreads();
        if (tid < 64)
            o[(size_t)b * Hsz + hd * DHEAD + tid] = rnd_tf32(red[tid] + red[tid + 64]);
    }
}

// ---------------- GNN helpers ----------------
__global__ __launch_bounds__(256) void scatterT_kernel(
    const float* __restrict__ hidden, const int* __restrict__ sku,
    float* __restrict__ peT)
{
    int b = blockIdx.x, tid = threadIdx.x;
    peT[(size_t)tid * Psz + sku[b]] = hidden[(size_t)b * Hsz + tid];
}

// fused: degree sum + tf32-round adj row
__global__ __launch_bounds__(256) void deg_round_kernel(
    const float* __restrict__ adj, float* __restrict__ adjr, float* __restrict__ scale)
{
    int p = blockIdx.x, tid = threadIdx.x;
    float s = 0.f;
    const float* row = &adj[(size_t)p * Psz];
    float* rowr = &adjr[(size_t)p * Psz];
    #pragma unroll
    for (int u = 0; u < 2; u++) {
        int f4 = tid + u * 256;
        float4 v = *(const float4*)&row[f4 * 4];
        s += v.x + v.y + v.z + v.w;
        v.x = rnd_tf32(v.x); v.y = rnd_tf32(v.y); v.z = rnd_tf32(v.z); v.w = rnd_tf32(v.w);
        *(float4*)&rowr[f4 * 4] = v;
    }
    __shared__ float red[256];
    red[tid] = s; __syncthreads();
    for (int off = 128; off; off >>= 1) {
        if (tid < off) red[tid] += red[tid + off];
        __syncthreads();
    }
    if (tid == 0) scale[p] = 1.0f / fmaxf(red[0], 1e-6f);
}

__global__ __launch_bounds__(256) void geluln_kernel(
    float* __restrict__ x, const float* __restrict__ g,
    const float* __restrict__ b)
{
    int p = blockIdx.x, tid = threadIdx.x;
    float v = x[(size_t)p * Hsz + tid];
    float ge = 0.5f * v * (1.0f + erff(v * 0.70710678118654752f));
    __shared__ float red[256];
    red[tid] = ge; __syncthreads();
    for (int off = 128; off; off >>= 1) {
        if (tid < off) red[tid] += red[tid + off];
        __syncthreads();
    }
    float mu = red[0] * (1.0f / Hsz);
    __syncthreads();
    float d = ge - mu;
    red[tid] = d * d; __syncthreads();
    for (int off = 128; off; off >>= 1) {
        if (tid < off) red[tid] += red[tid + off];
        __syncthreads();
    }
    float var = red[0] * (1.0f / Hsz);
    x[(size_t)p * Hsz + tid] = d * rsqrtf(var + 1e-5f) * g[tid] + b[tid];
}

// ---------------- cat build: [hidden | rnd(enriched)] ----------------
__global__ __launch_bounds__(256) void cat_kernel(
    const float* __restrict__ hidden, const float* __restrict__ trans,
    const int* __restrict__ sku, float* __restrict__ cat)
{
    int b = blockIdx.x, tid = threadIdx.x;
    cat[(size_t)b * 512 + tid] = hidden[(size_t)b * Hsz + tid];
    cat[(size_t)b * 512 + 256 + tid] = rnd_tf32(trans[(size_t)sku[b] * Hsz + tid]);
}

// ---------------- final epilogue ----------------
__global__ __launch_bounds__(256) void final_epi_kernel(
    const float* __restrict__ gatep, const float* __restrict__ hidden,
    const float* __restrict__ trans, const int* __restrict__ sku,
    const float* __restrict__ out_w, const float* __restrict__ out_b,
    float* __restrict__ out)
{
    int b = blockIdx.x, tid = threadIdx.x;
    float gt = sigmoidf_(gatep[(size_t)b * Hsz + tid]);
    float enr = trans[(size_t)sku[b] * Hsz + tid];
    float hid = hidden[(size_t)b * Hsz + tid];
    float comb = gt * enr + (1.0f - gt) * hid;
    __shared__ float red[256];
    red[tid] = comb * out_w[tid];
    __syncthreads();
    for (int off = 128; off; off >>= 1) {
        if (tid < off) red[tid] += red[tid + off];
        __syncthreads();
    }
    if (tid == 0) out[b] = red[0] + out_b[0];
}

// ---------------- launch ----------------
#define LSTM_SMEM 199680
#define MM_SMEM 73728
// g_wr offsets (floats)
#define WR_WIH0 0
#define WR_WIH1 262144
#define WR_KV   524288
#define WR_AO   655360
#define WR_GNN  720896
#define WR_Q    786432
#define WR_GATE 851968

extern "C" void kernel_launch(void* const* d_in, const int* in_sizes, int n_in,
                              void* d_out, int out_size)
{
    const float* x          = (const float*)d_in[0];
    const int*   sku        = (const int*)  d_in[1];
    const float* adj        = (const float*)d_in[2];
    const float* vsn_emb_w  = (const float*)d_in[3];
    const float* vsn_emb_b  = (const float*)d_in[4];
    const float* vsn_sel_w  = (const float*)d_in[5];
    const float* vsn_sel_b  = (const float*)d_in[6];
    const float* Wih0       = (const float*)d_in[7];
    const float* Whh0       = (const float*)d_in[8];
    const float* bih0       = (const float*)d_in[9];
    const float* bhh0       = (const float*)d_in[10];
    const float* Wih1       = (const float*)d_in[11];
    const float* Whh1       = (const float*)d_in[12];
    const float* bih1       = (const float*)d_in[13];
    const float* bhh1       = (const float*)d_in[14];
    const float* attn_in_w  = (const float*)d_in[15];
    const float* attn_in_b  = (const float*)d_in[16];
    const float* attn_out_w = (const float*)d_in[17];
    const float* attn_out_b = (const float*)d_in[18];
    const float* gnn_w      = (const float*)d_in[19];
    const float* gnn_b      = (const float*)d_in[20];
    const float* ln_g       = (const float*)d_in[21];
    const float* ln_b       = (const float*)d_in[22];
    const float* gate_w     = (const float*)d_in[23];
    const float* gate_b     = (const float*)d_in[24];
    const float* out_w      = (const float*)d_in[25];
    const float* out_b      = (const float*)d_in[26];
    float* out = (float*)d_out;

    static float *hP = nullptr, *xpP, *qP, *qgP, *oP, *hidP, *peTP, *degP, *aggP, *transP,
                 *catP, *gpP, *wrP, *adjrP, *partP;
    if (!hP) {
        cudaGetSymbolAddress((void**)&hP, g_h);
        cudaGetSymbolAddress((void**)&xpP, g_xp);
        cudaGetSymbolAddress((void**)&qP, g_q);
        cudaGetSymbolAddress((void**)&qgP, g_qg);
        cudaGetSymbolAddress((void**)&oP, g_o);
        cudaGetSymbolAddress((void**)&hidP, g_hidden);
        cudaGetSymbolAddress((void**)&degP, g_degs);
        cudaGetSymbolAddress((void**)&peTP, g_peT);
        cudaGetSymbolAddress((void**)&aggP, g_agg);
        cudaGetSymbolAddress((void**)&transP, g_trans);
        cudaGetSymbolAddress((void**)&catP, g_cat);
        cudaGetSymbolAddress((void**)&gpP, g_gatep);
        cudaGetSymbolAddress((void**)&wrP, g_wr);
        cudaGetSymbolAddress((void**)&adjrP, g_adjr);
        cudaGetSymbolAddress((void**)&partP, g_part);
        cudaFuncSetAttribute(lstm_persist, cudaFuncAttributeMaxDynamicSharedMemorySize, LSTM_SMEM);
        cudaFuncSetAttribute(mm_nt_tf32, cudaFuncAttributeMaxDynamicSharedMemorySize, MM_SMEM);
    }

    // weight pre-rounding (one fused launch) + VSN
    round_all<<<960, 256>>>(Wih0, Wih1, attn_in_w + (size_t)Hsz*Hsz, attn_out_w,
                            gnn_w, attn_in_w, gate_w, wrP);
    vsn_kernel<<<BT / 8, 256>>>(x, vsn_emb_w, vsn_emb_b, vsn_sel_w, vsn_sel_b, hP);

    // LSTM layer 0
    mm_nt_tf32<<<dim3(8, BT / 128), 256, MM_SMEM>>>(hP, wrP + WR_WIH0, bih0, bhh0, nullptr,
                                                    xpP, 1024, 256, 256, 0, 0);
    lstm_persist<<<NCTA, 256, LSTM_SMEM>>>(xpP, hP, Whh0);

    // LSTM layer 1
    mm_nt_tf32<<<dim3(8, BT / 128), 256, MM_SMEM>>>(hP, wrP + WR_WIH1, bih1, bhh1, nullptr,
                                                    xpP, 1024, 256, 256, 0, 0);
    lstm_persist<<<NCTA, 256, LSTM_SMEM>>>(xpP, hP, Whh1);

    // k,v projection; q via gather + GEMM
    mm_nt_tf32<<<dim3(4, BT / 128), 256, MM_SMEM>>>(hP, wrP + WR_KV, attn_in_b + Hsz, nullptr,
                                                    nullptr, xpP, 512, 256, 256, 0, 0);
    qgather_kernel<<<Bsz, 256>>>(hP, qgP);
    mm_nt_tf32<<<dim3(2, Bsz / 128), 256, MM_SMEM>>>(qgP, wrP + WR_Q, attn_in_b, nullptr,
                                                     nullptr, qP, 256, 256, 256, 0, 0);

    // attention at last query (o tf32-rounded)
    attn_last_kernel<<<dim3(Bsz, NHEADS), 128>>>(qP, xpP, oP);

    // output projection (hidden tf32-rounded)
    mm_nt_tf32<<<dim3(2, Bsz / 128), 256, MM_SMEM>>>(oP, wrP + WR_AO, attn_out_b, nullptr,
                                                     nullptr, hidP, 256, 256, 256, 1, 0);

    // GNN
    cudaMemsetAsync(peTP, 0, (size_t)Hsz * Psz * sizeof(float));
    scatterT_kernel<<<Bsz, 256>>>(hidP, sku, peTP);
    deg_round_kernel<<<Psz, 256>>>(adj, adjrP, degP);
    mm_nt_tf32<<<dim3(2, Psz / 128, 4), 256, MM_SMEM>>>(adjrP, peTP, nullptr, nullptr, nullptr,
                                                        partP, 256, 2048, 512, 0, (size_t)PH);
    agg_reduce<<<Psz, 256>>>(partP, degP, aggP);
    mm_nt_tf32<<<dim3(2, Psz / 128), 256, MM_SMEM>>>(aggP, wrP + WR_GNN, gnn_b, nullptr,
                                                     nullptr, transP, 256, 256, 256, 0, 0);
    geluln_kernel<<<Psz, 256>>>(transP, ln_g, ln_b);

    // gate via GEMM + epilogue
    cat_kernel<<<Bsz, 256>>>(hidP, transP, sku, catP);
    mm_nt_tf32<<<dim3(2, Bsz / 128), 256, MM_SMEM>>>(catP, wrP + WR_GATE, gate_b, nullptr,
                                                     nullptr, gpP, 256, 512, 512, 0, 0);
    final_epi_kernel<<<Bsz, 256>>>(gpP, hidP, transP, sku, out_w, out_b, out);
}

// round 15
// speedup vs baseline: 1.3895x; 1.3895x over previous
#include <cuda_runtime.h>
#include <cuda_bf16.h>
#include <math.h>
#include <stdint.h>

// Problem constants
#define Bsz 1024
#define Tsz 128
#define Fsz 9
#define Hsz 256
#define Psz 2048
#define NHEADS 4
#define DHEAD 64
#define BT (Bsz*Tsz)
#define NCTA 128
#define PH (Psz*Hsz)

// ---------------- scratch (static device globals; no allocation) ----------------
__device__ float g_h[BT * Hsz];        // VSN out / LSTM hseq (tf32-rounded at write)
__device__ float g_xp[BT * 4 * Hsz];   // xp precompute / kv buffer (full fp32)
__device__ float g_q[Bsz * Hsz];       // q projection out
__device__ float g_qg[Bsz * Hsz];      // gathered h_last (tf32-valued)
__device__ float g_o[Bsz * Hsz];       // attention out (tf32-rounded)
__device__ float g_hidden[Bsz * Hsz];  // (tf32-rounded via roundC)
__device__ float g_peT[Hsz * Psz];     // transposed product embeds [h][p]
__device__ float g_degs[Psz];
__device__ float g_agg[Psz * Hsz];     // (tf32-rounded in reduce)
__device__ float g_trans[Psz * Hsz];
__device__ float g_cat[Bsz * 512];     // [hidden | rounded enriched]
__device__ float g_gatep[Bsz * Hsz];   // gate preactivation
__device__ float g_wr[983040];         // rounded weights
__device__ float g_adjr[Psz * Psz];    // rounded adj
__device__ float g_part[4 * PH];       // split-K partials for adj GEMM

// per-group barrier counters (16 groups; monotonic, separate cache lines)
__device__ unsigned g_grp_cnt[16 * 32];

__device__ __forceinline__ float sigmoidf_(float x) { return 1.0f / (1.0f + expf(-x)); }

// ---------------- helpers (target-independent PTX) ----------------
__device__ __forceinline__ uint32_t f2tf32(float f) {
    uint32_t r;
    asm("cvt.rna.tf32.f32 %0, %1;" : "=r"(r) : "f"(f));
    return r;
}
__device__ __forceinline__ float rnd_tf32(float f) { return __uint_as_float(f2tf32(f)); }
__device__ __forceinline__ void mma_m16n8k8(float d[4], const uint32_t a[4], const uint32_t b[2]) {
    asm volatile(
        "mma.sync.aligned.m16n8k8.row.col.f32.tf32.tf32.f32 "
        "{%0,%1,%2,%3}, {%4,%5,%6,%7}, {%8,%9}, {%0,%1,%2,%3};"
        : "+f"(d[0]), "+f"(d[1]), "+f"(d[2]), "+f"(d[3])
        : "r"(a[0]), "r"(a[1]), "r"(a[2]), "r"(a[3]), "r"(b[0]), "r"(b[1]));
}
__device__ __forceinline__ uint32_t smem_u32(const void* p) {
    uint32_t a;
    asm("{ .reg .u64 t; cvta.to.shared.u64 t, %1; cvt.u32.u64 %0, t; }" : "=r"(a) : "l"(p));
    return a;
}
__device__ __forceinline__ void ldsm_x4(uint32_t r[4], uint32_t addr) {
    asm volatile("ldmatrix.sync.aligned.m8n8.x4.shared.b16 {%0,%1,%2,%3}, [%4];"
                 : "=r"(r[0]), "=r"(r[1]), "=r"(r[2]), "=r"(r[3]) : "r"(addr));
}
__device__ __forceinline__ void ldsm_x2(uint32_t r[2], uint32_t addr) {
    asm volatile("ldmatrix.sync.aligned.m8n8.x2.shared.b16 {%0,%1}, [%2];"
                 : "=r"(r[0]), "=r"(r[1]) : "r"(addr));
}
__device__ __forceinline__ void cp_async16(uint32_t dst, const void* src) {
    asm volatile("cp.async.cg.shared.global [%0], [%1], 16;" :: "r"(dst), "l"(src));
}
__device__ __forceinline__ void cp_commit() {
    asm volatile("cp.async.commit_group;" ::: "memory");
}
template<int N> __device__ __forceinline__ void cp_wait() {
    asm volatile("cp.async.wait_group %0;" :: "n"(N) : "memory");
}

// ---------------- round_all: fused RNE rounding of all 7 weight blobs ----------------
__global__ __launch_bounds__(256) void round_all(
    const float* __restrict__ s0, const float* __restrict__ s1,
    const float* __restrict__ s2, const float* __restrict__ s3,
    const float* __restrict__ s4, const float* __restrict__ s5,
    const float* __restrict__ s6, float* __restrict__ dst)
{
    int i = blockIdx.x * 256 + threadIdx.x;
    if (i >= 245760) return;
    const float* src; int off;
    if      (i < 65536)  { src = s0; off = 0; }
    else if (i < 131072) { src = s1; off = 65536; }
    else if (i < 163840) { src = s2; off = 131072; }
    else if (i < 180224) { src = s3; off = 163840; }
    else if (i < 196608) { src = s4; off = 180224; }
    else if (i < 212992) { src = s5; off = 196608; }
    else                 { src = s6; off = 212992; }
    float4 v = ((const float4*)src)[i - off];
    v.x = rnd_tf32(v.x); v.y = rnd_tf32(v.y); v.z = rnd_tf32(v.z); v.w = rnd_tf32(v.w);
    ((float4*)dst)[i] = v;
}

// ================= persistent LSTM layer (R13-proven version, verbatim) =================
__global__ __launch_bounds__(256) void lstm_persist(
    const float* __restrict__ xp, float* __restrict__ hseq,
    const float* __restrict__ Whh)
{
    extern __shared__ char sbuf[];
    uint32_t (*As)[260] = (uint32_t(*)[260])sbuf;
    uint32_t (*Bs)[260] = (uint32_t(*)[260])(sbuf + 66560);
    float (*Cs)[132]    = (float(*)[132])sbuf;   // aliases As

    const int tid = threadIdx.x;
    const int wid = tid >> 5, lane = tid & 31;
    const int wr = wid & 1, wc = wid >> 1;
    const int grp = blockIdx.x >> 3;
    const int m0 = grp * 64;
    const int j0 = (blockIdx.x & 7) * 32;
    unsigned* cntP = &g_grp_cnt[grp * 32];

    const uint32_t asBase = smem_u32(&As[0][0]);
    const uint32_t bsBase = smem_u32(&Bs[0][0]);

    for (int i = tid; i < 128 * 64; i += 256) {
        int r = i >> 6, cc = (i & 63) << 2;
        int wrow = (r >> 5) * 256 + j0 + (r & 31);
        float4 v = *(const float4*)&Whh[(size_t)wrow * 256 + cc];
        uint32_t* p = &Bs[r][cc];
        p[0] = f2tf32(v.x); p[1] = f2tf32(v.y); p[2] = f2tf32(v.z); p[3] = f2tf32(v.w);
    }

    const int lg = lane >> 3, lr8 = lane & 7;
    uint32_t aAddr[2], bAddr[4];
    #pragma unroll
    for (int mi = 0; mi < 2; mi++)
        aAddr[mi] = asBase + (uint32_t)(wr * 32 + mi * 16 + lr8 + (lg & 1) * 8) * 1040u
                    + (uint32_t)((lg >> 1) * 4) * 4u;
    #pragma unroll
    for (int ni = 0; ni < 4; ni++)
        bAddr[ni] = bsBase + (uint32_t)(wc * 32 + ni * 8 + lr8) * 1040u
                    + (uint32_t)((lg & 1) * 4) * 4u;

    const int srow = tid >> 2, sc0 = tid & 3;
    const uint32_t sdst0 = asBase + (uint32_t)srow * 1040u;

    const int bl = tid >> 2, jl0 = (tid & 3) * 8;
    const int b = m0 + bl;
    float creg[8];
    unsigned base = 0;

    // ---- t = 0 ----
    {
        const float* xb = &xp[((size_t)b * Tsz + 0) * 1024 + j0 + jl0];
        float xi[8], xg[8], xo[8], hn[8];
        *(float4*)&xi[0] = *(const float4*)&xb[0];    *(float4*)&xi[4] = *(const float4*)&xb[4];
        *(float4*)&xg[0] = *(const float4*)&xb[512];  *(float4*)&xg[4] = *(const float4*)&xb[516];
        *(float4*)&xo[0] = *(const float4*)&xb[768];  *(float4*)&xo[4] = *(const float4*)&xb[772];
        #pragma unroll
        for (int e = 0; e < 8; e++) {
            creg[e] = sigmoidf_(xi[e]) * tanhf(xg[e]);
            hn[e] = rnd_tf32(sigmoidf_(xo[e]) * tanhf(creg[e]));
        }
        float* hb = &hseq[((size_t)b * Tsz + 0) * 256 + j0 + jl0];
        *(float4*)&hb[0] = *(float4*)&hn[0];  *(float4*)&hb[4] = *(float4*)&hn[4];
    }
    __syncthreads();
    if (tid == 0) {
        unsigned arr;
        asm volatile("atom.release.gpu.add.u32 %0, [%1], 1;" : "=r"(arr) : "l"(cntP) : "memory");
        base = arr & ~7u;
    }

    for (int t = 1; t < Tsz; t++) {
        // prefetch xp (overlaps inter-CTA wait)
        const float* xb = &xp[((size_t)b * Tsz + t) * 1024 + j0 + jl0];
        float xi[8], xf[8], xg[8], xo[8];
        *(float4*)&xi[0] = *(const float4*)&xb[0];    *(float4*)&xi[4] = *(const float4*)&xb[4];
        *(float4*)&xf[0] = *(const float4*)&xb[256];  *(float4*)&xf[4] = *(const float4*)&xb[260];
        *(float4*)&xg[0] = *(const float4*)&xb[512];  *(float4*)&xg[4] = *(const float4*)&xb[516];
        *(float4*)&xo[0] = *(const float4*)&xb[768];  *(float4*)&xo[4] = *(const float4*)&xb[772];

        if (tid == 0) {
            unsigned target = base + 8u * (unsigned)t;
            unsigned c;
            do {
                asm volatile("ld.acquire.gpu.u32 %0, [%1];" : "=r"(c) : "l"(cntP) : "memory");
            } while ((int)(c - target) < 0);
        }
        __syncthreads();

        {
            const float* srcrow = &hseq[((size_t)(m0 + srow) * Tsz + (t - 1)) * 256];
            #pragma unroll
            for (int u = 0; u < 8; u++) {
                int cf4 = sc0 + u * 4;
                cp_async16(sdst0 + (uint32_t)cf4 * 16u, srcrow + cf4 * 4);
            }
            cp_commit();
            #pragma unroll
            for (int u = 8; u < 16; u++) {
                int cf4 = sc0 + u * 4;
                cp_async16(sdst0 + (uint32_t)cf4 * 16u, srcrow + cf4 * 4);
            }
            cp_commit();
        }

        float d[2][4][4] = {};
        cp_wait<1>();
        __syncthreads();
        #pragma unroll 8
        for (int k8 = 0; k8 < 16; k8++) {
            const uint32_t off = (uint32_t)k8 * 32u;
            uint32_t a[2][4], bfr[4][2];
            #pragma unroll
            for (int mi = 0; mi < 2; mi++) ldsm_x4(a[mi], aAddr[mi] + off);
            #pragma unroll
            for (int ni = 0; ni < 4; ni++) ldsm_x2(bfr[ni], bAddr[ni] + off);
            #pragma unroll
            for (int mi = 0; mi < 2; mi++)
                #pragma unroll
                for (int ni = 0; ni < 4; ni++)
                    mma_m16n8k8(d[mi][ni], a[mi], bfr[ni]);
        }
        cp_wait<0>();
        __syncthreads();
        #pragma unroll 8
        for (int k8 = 16; k8 < 32; k8++) {
            const uint32_t off = (uint32_t)k8 * 32u;
            uint32_t a[2][4], bfr[4][2];
            #pragma unroll
            for (int mi = 0; mi < 2; mi++) ldsm_x4(a[mi], aAddr[mi] + off);
            #pragma unroll
            for (int ni = 0; ni < 4; ni++) ldsm_x2(bfr[ni], bAddr[ni] + off);
            #pragma unroll
            for (int mi = 0; mi < 2; mi++)
                #pragma unroll
                for (int ni = 0; ni < 4; ni++)
                    mma_m16n8k8(d[mi][ni], a[mi], bfr[ni]);
        }
        __syncthreads();

        const int gID = lane >> 2, tig = lane & 3;
        #pragma unroll
        for (int mi = 0; mi < 2; mi++) {
            int m = wr * 32 + mi * 16 + gID;
            #pragma unroll
            for (int ni = 0; ni < 4; ni++) {
                int n = wc * 32 + ni * 8 + tig * 2;
                *(float2*)&Cs[m][n]     = make_float2(d[mi][ni][0], d[mi][ni][1]);
                *(float2*)&Cs[m + 8][n] = make_float2(d[mi][ni][2], d[mi][ni][3]);
            }
        }
        __syncthreads();

        float hn[8];
        #pragma unroll
        for (int e = 0; e < 8; e++) {
            int jl = jl0 + e;
            float gi = Cs[bl][jl]      + xi[e];
            float gf = Cs[bl][32 + jl] + xf[e];
            float gg = Cs[bl][64 + jl] + xg[e];
            float go = Cs[bl][96 + jl] + xo[e];
            creg[e] = sigmoidf_(gf) * creg[e] + sigmoidf_(gi) * tanhf(gg);
            hn[e] = rnd_tf32(sigmoidf_(go) * tanhf(creg[e]));
        }
        float* hb = &hseq[((size_t)b * Tsz + t) * 256 + j0 + jl0];
        *(float4*)&hb[0] = *(float4*)&hn[0];  *(float4*)&hb[4] = *(float4*)&hn[4];

        __syncthreads();
        if (tid == 0)
            asm volatile("red.release.gpu.add.u32 [%0], 1;" :: "l"(cntP) : "memory");
    }
}

// ================= mm_nt_tf32 v2: cp.async double-buffered, CTA 128x128, split-K =================
__global__ __launch_bounds__(256) void mm_nt_tf32(
    const float* __restrict__ A, const float* __restrict__ W,
    const float* __restrict__ b1, const float* __restrict__ b2,
    const float* __restrict__ rs,
    float* __restrict__ C, int Nall, int lda, int Kchunk, int roundC, size_t partStride)
{
    extern __shared__ char mmbuf[];
    const uint32_t sb = smem_u32(mmbuf);
    const int tid = threadIdx.x;
    const int wid = tid >> 5, lane = tid & 31;
    const int gID = lane >> 2, tig = lane & 3;
    const int wr = wid & 3, wc = wid >> 2;
    const int m0 = blockIdx.y * 128, n0 = blockIdx.x * 128;
    const int kStart = blockIdx.z * Kchunk;
    C += (size_t)blockIdx.z * partStride;

    const int lg = lane >> 3, lr8 = lane & 7;
    uint32_t aOff[2], bOff[4];
    #pragma unroll
    for (int mi = 0; mi < 2; mi++)
        aOff[mi] = (uint32_t)(wr * 32 + mi * 16 + lr8 + (lg & 1) * 8) * 144u
                   + (uint32_t)((lg >> 1) * 4) * 4u;
    #pragma unroll
    for (int ni = 0; ni < 4; ni++)
        bOff[ni] = 18432u + (uint32_t)(wc * 64 + ni * 16 + (lg >> 1) * 8 + lr8) * 144u
                   + (uint32_t)((lg & 1) * 4) * 4u;

    float d[2][8][4] = {};
    const int nk = Kchunk >> 5;

    auto load_stage = [&](int kc, int s) {
        const int k0 = kStart + (kc << 5);
        const uint32_t base = sb + (uint32_t)s * 36864u;
        #pragma unroll
        for (int i = 0; i < 4; i++) {
            int idx = tid + i * 256;
            int r = idx >> 3, c16 = idx & 7;
            cp_async16(base + (uint32_t)r * 144u + (uint32_t)c16 * 16u,
                       &A[(size_t)(m0 + r) * lda + k0 + c16 * 4]);
        }
        #pragma unroll
        for (int i = 0; i < 4; i++) {
            int idx = tid + i * 256;
            int r = idx >> 3, c16 = idx & 7;
            cp_async16(base + 18432u + (uint32_t)r * 144u + (uint32_t)c16 * 16u,
                       &W[(size_t)(n0 + r) * lda + k0 + c16 * 4]);
        }
        cp_commit();
    };

    load_stage(0, 0);
    for (int kc = 0; kc < nk; kc++) {
        const int s = kc & 1;
        const uint32_t stBase = sb + (uint32_t)s * 36864u;
        if (kc + 1 < nk) {
            load_stage(kc + 1, s ^ 1);
            cp_wait<1>();
        } else {
            cp_wait<0>();
        }
        __syncthreads();
        #pragma unroll
        for (int k8 = 0; k8 < 4; k8++) {
            const uint32_t off = stBase + (uint32_t)k8 * 32u;
            uint32_t a[2][4], b[4][4];
            #pragma unroll
            for (int mi = 0; mi < 2; mi++) ldsm_x4(a[mi], off + aOff[mi]);
            #pragma unroll
            for (int ni = 0; ni < 4; ni++) ldsm_x4(b[ni], off + bOff[ni]);
            #pragma unroll
            for (int mi = 0; mi < 2; mi++)
                #pragma unroll
                for (int ni = 0; ni < 4; ni++) {
                    mma_m16n8k8(d[mi][ni * 2],     a[mi], &b[ni][0]);
                    mma_m16n8k8(d[mi][ni * 2 + 1], a[mi], &b[ni][2]);
                }
        }
        __syncthreads();
    }
    #pragma unroll
    for (int mi = 0; mi < 2; mi++) {
        int m = m0 + wr * 32 + mi * 16 + gID;
        float s0 = rs ? rs[m] : 1.0f;
        float s1 = rs ? rs[m + 8] : 1.0f;
        #pragma unroll
        for (int ni = 0; ni < 8; ni++) {
            int n = n0 + wc * 64 + ni * 8 + tig * 2;
            float bb0 = 0.f, bb1 = 0.f;
            if (b1) { bb0 += b1[n]; bb1 += b1[n + 1]; }
            if (b2) { bb0 += b2[n]; bb1 += b2[n + 1]; }
            float v00 = d[mi][ni][0] * s0 + bb0;
            float v01 = d[mi][ni][1] * s0 + bb1;
            float v10 = d[mi][ni][2] * s1 + bb0;
            float v11 = d[mi][ni][3] * s1 + bb1;
            if (roundC) { v00 = rnd_tf32(v00); v01 = rnd_tf32(v01);
                          v10 = rnd_tf32(v10); v11 = rnd_tf32(v11); }
            C[(size_t)m * Nall + n]           = v00;
            C[(size_t)m * Nall + n + 1]       = v01;
            C[(size_t)(m + 8) * Nall + n]     = v10;
            C[(size_t)(m + 8) * Nall + n + 1] = v11;
        }
    }
}

// ---------------- reduce split-K partials -> agg ----------------
__global__ __launch_bounds__(256) void agg_reduce(
    const float* __restrict__ part, const float* __restrict__ degscale,
    float* __restrict__ agg)
{
    int p = blockIdx.x, h = threadIdx.x;
    size_t i = (size_t)p * Hsz + h;
    float s = part[i] + part[i + PH] + part[i + 2 * (size_t)PH] + part[i + 3 * (size_t)PH];
    agg[i] = rnd_tf32(s * degscale[p]);
}

// ---------------- VSN: one warp per (b,t); outputs tf32-rounded ----------------
__global__ __launch_bounds__(256) void vsn_kernel(
    const float* __restrict__ x,
    const float* __restrict__ emb_w, const float* __restrict__ emb_b,
    const float* __restrict__ sel_w, const float* __restrict__ sel_b,
    float* __restrict__ h)
{
    const int lane = threadIdx.x & 31;
    const size_t bt = (size_t)blockIdx.x * 8 + (threadIdx.x >> 5);
    float xv = (lane < Fsz) ? x[bt * Fsz + lane] : 0.f;
    float xs[Fsz];
    #pragma unroll
    for (int f = 0; f < Fsz; f++) xs[f] = __shfl_sync(0xffffffffu, xv, f);
    float lg = -1e30f;
    if (lane < Fsz) {
        lg = sel_b[lane];
        #pragma unroll
        for (int j = 0; j < Fsz; j++) lg += xs[j] * sel_w[lane * Fsz + j];
    }
    float mx = lg;
    #pragma unroll
    for (int off = 16; off; off >>= 1) mx = fmaxf(mx, __shfl_xor_sync(0xffffffffu, mx, off));
    float ex = (lane < Fsz) ? expf(lg - mx) : 0.f;
    float den = ex;
    #pragma unroll
    for (int off = 16; off; off >>= 1) den += __shfl_xor_sync(0xffffffffu, den, off);
    float wv = ex / den;
    float wf[Fsz];
    #pragma unroll
    for (int f = 0; f < Fsz; f++) wf[f] = __shfl_sync(0xffffffffu, wv, f);

    const int o0 = lane * 8;
    float acc[8] = {};
    #pragma unroll
    for (int f = 0; f < Fsz; f++) {
        float4 w0 = *(const float4*)&emb_w[f * Hsz + o0];
        float4 w1 = *(const float4*)&emb_w[f * Hsz + o0 + 4];
        float4 c0 = *(const float4*)&emb_b[f * Hsz + o0];
        float4 c1 = *(const float4*)&emb_b[f * Hsz + o0 + 4];
        float wfx = wf[f], xf = xs[f];
        acc[0] += wfx * (xf * w0.x + c0.x); acc[1] += wfx * (xf * w0.y + c0.y);
        acc[2] += wfx * (xf * w0.z + c0.z); acc[3] += wfx * (xf * w0.w + c0.w);
        acc[4] += wfx * (xf * w1.x + c1.x); acc[5] += wfx * (xf * w1.y + c1.y);
        acc[6] += wfx * (xf * w1.z + c1.z); acc[7] += wfx * (xf * w1.w + c1.w);
    }
    #pragma unroll
    for (int e = 0; e < 8; e++) acc[e] = rnd_tf32(acc[e]);
    float* hb = &h[bt * Hsz + o0];
    *(float4*)&hb[0] = *(float4*)&acc[0];
    *(float4*)&hb[4] = *(float4*)&acc[4];
}

// ---------------- gather h_last ----------------
__global__ __launch_bounds__(256) void qgather_kernel(
    const float* __restrict__ h, float* __restrict__ qg)
{
    int b = blockIdx.x, tid = threadIdx.x;
    qg[(size_t)b * Hsz + tid] = h[((size_t)b * Tsz + (Tsz - 1)) * Hsz + tid];
}

// ---------------- attention (last query only); v-sum parallel over 128 threads ----------------
__global__ __launch_bounds__(128) void attn_last_kernel(
    const float* __restrict__ q, const float* __restrict__ kv,
    float* __restrict__ o)
{
    int b = blockIdx.x, hd = blockIdx.y;
    int tid = threadIdx.x;
    __shared__ float qs[DHEAD];
    __shared__ float sc[Tsz];
    __shared__ float red[Tsz];
    if (tid < DHEAD) qs[tid] = q[(size_t)b * Hsz + hd * DHEAD + tid];
    __syncthreads();
    const float* kp = &kv[((size_t)b * Tsz + tid) * 512 + hd * DHEAD];
    float s = 0.f;
#pragma unroll 8
    for (int d = 0; d < DHEAD; d++) s += qs[d] * kp[d];
    s *= 0.125f;
    sc[tid] = s;
    red[tid] = s;
    __syncthreads();
    for (int off = 64; off; off >>= 1) {
        if (tid < off) red[tid] = fmaxf(red[tid], red[tid + off]);
        __syncthreads();
    }
    float mx = red[0];
    __syncthreads();
    float e = expf(sc[tid] - mx);
    sc[tid] = e;
    red[tid] = e;
    __syncthreads();
    for (int off = 64; off; off >>= 1) {
        if (tid < off) red[tid] += red[tid + off];
        __syncthreads();
    }
    float inv = 1.0f / red[0];
    __syncthreads();
    sc[tid] *= inv;
    __syncthreads();
    {
        int dd = tid & 63, hf = tid >> 6;
        float acc = 0.f;
        const float* vbase = &kv[((size_t)b * Tsz + hf * 64) * 512 + 256 + hd * DHEAD + dd];
        #pragma unroll 8
        for (int t = 0; t < 64; t++)
            acc += sc[hf * 64 + t] * vbase[(size_t)t * 512];
        red[tid] = acc;
        __syncthreads();
        if (tid < 64)
            o[(size_t)b * Hsz + hd * DHEAD + tid] = rnd_tf32(red[tid] + red[tid + 64]);
    }
}

// ---------------- GNN helpers ----------------
__global__ __launch_bounds__(256) void scatterT_kernel(
    const float* __restrict__ hidden, const int* __restrict__ sku,
    float* __restrict__ peT)
{
    int b = blockIdx.x, tid = threadIdx.x;
    peT[(size_t)tid * Psz + sku[b]] = hidden[(size_t)b * Hsz + tid];
}

// fused: degree sum + tf32-round adj row
__global__ __launch_bounds__(256) void deg_round_kernel(
    const float* __restrict__ adj, float* __restrict__ adjr, float* __restrict__ scale)
{
    int p = blockIdx.x, tid = threadIdx.x;
    float s = 0.f;
    const float* row = &adj[(size_t)p * Psz];
    float* rowr = &adjr[(size_t)p * Psz];
    #pragma unroll
    for (int u = 0; u < 2; u++) {
        int f4 = tid + u * 256;
        float4 v = *(const float4*)&row[f4 * 4];
        s += v.x + v.y + v.z + v.w;
        v.x = rnd_tf32(v.x); v.y = rnd_tf32(v.y); v.z = rnd_tf32(v.z); v.w = rnd_tf32(v.w);
        *(float4*)&rowr[f4 * 4] = v;
    }
    __shared__ float red[256];
    red[tid] = s; __syncthreads();
    for (int off = 128; off; off >>= 1) {
        if (tid < off) red[tid] += red[tid + off];
        __syncthreads();
    }
    if (tid == 0) scale[p] = 1.0f / fmaxf(red[0], 1e-6f);
}

__global__ __launch_bounds__(256) void geluln_kernel(
    float* __restrict__ x, const float* __restrict__ g,
    const float* __restrict__ b)
{
    int p = blockIdx.x, tid = threadIdx.x;
    float v = x[(size_t)p * Hsz + tid];
    float ge = 0.5f * v * (1.0f + erff(v * 0.70710678118654752f));
    __shared__ float red[256];
    red[tid] = ge; __syncthreads();
    for (int off = 128; off; off >>= 1) {
        if (tid < off) red[tid] += red[tid + off];
        __syncthreads();
    }
    float mu = red[0] * (1.0f / Hsz);
    __syncthreads();
    float d = ge - mu;
    red[tid] = d * d; __syncthreads();
    for (int off = 128; off; off >>= 1) {
        if (tid < off) red[tid] += red[tid + off];
        __syncthreads();
    }
    float var = red[0] * (1.0f / Hsz);
    x[(size_t)p * Hsz + tid] = d * rsqrtf(var + 1e-5f) * g[tid] + b[tid];
}

// ---------------- cat build: [hidden | rnd(enriched)] ----------------
__global__ __launch_bounds__(256) void cat_kernel(
    const float* __restrict__ hidden, const float* __restrict__ trans,
    const int* __restrict__ sku, float* __restrict__ cat)
{
    int b = blockIdx.x, tid = threadIdx.x;
    cat[(size_t)b * 512 + tid] = hidden[(size_t)b * Hsz + tid];
    cat[(size_t)b * 512 + 256 + tid] = rnd_tf32(trans[(size_t)sku[b] * Hsz + tid]);
}

// ---------------- final epilogue ----------------
__global__ __launch_bounds__(256) void final_epi_kernel(
    const float* __restrict__ gatep, const float* __restrict__ hidden,
    const float* __restrict__ trans, const int* __restrict__ sku,
    const float* __restrict__ out_w, const float* __restrict__ out_b,
    float* __restrict__ out)
{
    int b = blockIdx.x, tid = threadIdx.x;
    float gt = sigmoidf_(gatep[(size_t)b * Hsz + tid]);
    float enr = trans[(size_t)sku[b] * Hsz + tid];
    float hid = hidden[(size_t)b * Hsz + tid];
    float comb = gt * enr + (1.0f - gt) * hid;
    __shared__ float red[256];
    red[tid] = comb * out_w[tid];
    __syncthreads();
    for (int off = 128; off; off >>= 1) {
        if (tid < off) red[tid] += red[tid + off];
        __syncthreads();
    }
    if (tid == 0) out[b] = red[0] + out_b[0];
}

// ---------------- launch ----------------
#define LSTM_SMEM 199680
#define MM_SMEM 73728
// g_wr offsets (floats)
#define WR_WIH0 0
#define WR_WIH1 262144
#define WR_KV   524288
#define WR_AO   655360
#define WR_GNN  720896
#define WR_Q    786432
#define WR_GATE 851968

extern "C" void kernel_launch(void* const* d_in, const int* in_sizes, int n_in,
                              void* d_out, int out_size)
{
    const float* x          = (const float*)d_in[0];
    const int*   sku        = (const int*)  d_in[1];
    const float* adj        = (const float*)d_in[2];
    const float* vsn_emb_w  = (const float*)d_in[3];
    const float* vsn_emb_b  = (const float*)d_in[4];
    const float* vsn_sel_w  = (const float*)d_in[5];
    const float* vsn_sel_b  = (const float*)d_in[6];
    const float* Wih0       = (const float*)d_in[7];
    const float* Whh0       = (const float*)d_in[8];
    const float* bih0       = (const float*)d_in[9];
    const float* bhh0       = (const float*)d_in[10];
    const float* Wih1       = (const float*)d_in[11];
    const float* Whh1       = (const float*)d_in[12];
    const float* bih1       = (const float*)d_in[13];
    const float* bhh1       = (const float*)d_in[14];
    const float* attn_in_w  = (const float*)d_in[15];
    const float* attn_in_b  = (const float*)d_in[16];
    const float* attn_out_w = (const float*)d_in[17];
    const float* attn_out_b = (const float*)d_in[18];
    const float* gnn_w      = (const float*)d_in[19];
    const float* gnn_b      = (const float*)d_in[20];
    const float* ln_g       = (const float*)d_in[21];
    const float* ln_b       = (const float*)d_in[22];
    const float* gate_w     = (const float*)d_in[23];
    const float* gate_b     = (const float*)d_in[24];
    const float* out_w      = (const float*)d_in[25];
    const float* out_b      = (const float*)d_in[26];
    float* out = (float*)d_out;

    static float *hP = nullptr, *xpP, *qP, *qgP, *oP, *hidP, *peTP, *degP, *aggP, *transP,
                 *catP, *gpP, *wrP, *adjrP, *partP;
    if (!hP) {
        cudaGetSymbolAddress((void**)&hP, g_h);
        cudaGetSymbolAddress((void**)&xpP, g_xp);
        cudaGetSymbolAddress((void**)&qP, g_q);
        cudaGetSymbolAddress((void**)&qgP, g_qg);
        cudaGetSymbolAddress((void**)&oP, g_o);
        cudaGetSymbolAddress((void**)&hidP, g_hidden);
        cudaGetSymbolAddress((void**)&degP, g_degs);
        cudaGetSymbolAddress((void**)&peTP, g_peT);
        cudaGetSymbolAddress((void**)&aggP, g_agg);
        cudaGetSymbolAddress((void**)&transP, g_trans);
        cudaGetSymbolAddress((void**)&catP, g_cat);
        cudaGetSymbolAddress((void**)&gpP, g_gatep);
        cudaGetSymbolAddress((void**)&wrP, g_wr);
        cudaGetSymbolAddress((void**)&adjrP, g_adjr);
        cudaGetSymbolAddress((void**)&partP, g_part);
        cudaFuncSetAttribute(lstm_persist, cudaFuncAttributeMaxDynamicSharedMemorySize, LSTM_SMEM);
        cudaFuncSetAttribute(mm_nt_tf32, cudaFuncAttributeMaxDynamicSharedMemorySize, MM_SMEM);
    }

    // weight pre-rounding (one fused launch) + VSN
    round_all<<<960, 256>>>(Wih0, Wih1, attn_in_w + (size_t)Hsz*Hsz, attn_out_w,
                            gnn_w, attn_in_w, gate_w, wrP);
    vsn_kernel<<<BT / 8, 256>>>(x, vsn_emb_w, vsn_emb_b, vsn_sel_w, vsn_sel_b, hP);

    // LSTM layer 0
    mm_nt_tf32<<<dim3(8, BT / 128), 256, MM_SMEM>>>(hP, wrP + WR_WIH0, bih0, bhh0, nullptr,
                                                    xpP, 1024, 256, 256, 0, 0);
    lstm_persist<<<NCTA, 256, LSTM_SMEM>>>(xpP, hP, Whh0);

    // LSTM layer 1
    mm_nt_tf32<<<dim3(8, BT / 128), 256, MM_SMEM>>>(hP, wrP + WR_WIH1, bih1, bhh1, nullptr,
                                                    xpP, 1024, 256, 256, 0, 0);
    lstm_persist<<<NCTA, 256, LSTM_SMEM>>>(xpP, hP, Whh1);

    // k,v projection; q via gather + GEMM
    mm_nt_tf32<<<dim3(4, BT / 128), 256, MM_SMEM>>>(hP, wrP + WR_KV, attn_in_b + Hsz, nullptr,
                                                    nullptr, xpP, 512, 256, 256, 0, 0);
    qgather_kernel<<<Bsz, 256>>>(hP, qgP);
    mm_nt_tf32<<<dim3(2, Bsz / 128), 256, MM_SMEM>>>(qgP, wrP + WR_Q, attn_in_b, nullptr,
                                                     nullptr, qP, 256, 256, 256, 0, 0);

    // attention at last query (o tf32-rounded)
    attn_last_kernel<<<dim3(Bsz, NHEADS), 128>>>(qP, xpP, oP);

    // output projection (hidden tf32-rounded)
    mm_nt_tf32<<<dim3(2, Bsz / 128), 256, MM_SMEM>>>(oP, wrP + WR_AO, attn_out_b, nullptr,
                                                     nullptr, hidP, 256, 256, 256, 1, 0);

    // GNN
    cudaMemsetAsync(peTP, 0, (size_t)Hsz * Psz * sizeof(float));
    scatterT_kernel<<<Bsz, 256>>>(hidP, sku, peTP);
    deg_round_kernel<<<Psz, 256>>>(adj, adjrP, degP);
    mm_nt_tf32<<<dim3(2, Psz / 128, 4), 256, MM_SMEM>>>(adjrP, peTP, nullptr, nullptr, nullptr,
                                                        partP, 256, 2048, 512, 0, (size_t)PH);
    agg_reduce<<<Psz, 256>>>(partP, degP, aggP);
    mm_nt_tf32<<<dim3(2, Psz / 128), 256, MM_SMEM>>>(aggP, wrP + WR_GNN, gnn_b, nullptr,
                                                     nullptr, transP, 256, 256, 256, 0, 0);
    geluln_kernel<<<Psz, 256>>>(transP, ln_g, ln_b);

    // gate via GEMM + epilogue
    cat_kernel<<<Bsz, 256>>>(hidP, transP, sku, catP);
    mm_nt_tf32<<<dim3(2, Bsz / 128), 256, MM_SMEM>>>(catP, wrP + WR_GATE, gate_b, nullptr,
                                                     nullptr, gpP, 256, 512, 512, 0, 0);
    final_epi_kernel<<<Bsz, 256>>>(gpP, hidP, transP, sku, out_w, out_b, out);
}

// round 16
// speedup vs baseline: 1.5602x; 1.1228x over previous
#include <cuda_runtime.h>
#include <cuda_bf16.h>
#include <math.h>
#include <stdint.h>

// Problem constants
#define Bsz 1024
#define Tsz 128
#define Fsz 9
#define Hsz 256
#define Psz 2048
#define NHEADS 4
#define DHEAD 64
#define BT (Bsz*Tsz)
#define NCTA 128
#define PH (Psz*Hsz)

// ---------------- scratch (static device globals; no allocation) ----------------
__device__ float g_h[BT * Hsz];        // VSN out / LSTM hseq (tf32-rounded at write)
__device__ float g_xp[BT * 4 * Hsz];   // xp precompute / kv buffer (full fp32)
__device__ float g_q[Bsz * Hsz];       // q projection out
__device__ float g_qg[Bsz * Hsz];      // gathered h_last (tf32-valued)
__device__ float g_o[Bsz * Hsz];       // attention out (tf32-rounded)
__device__ float g_hidden[Bsz * Hsz];  // (tf32-rounded via roundC)
__device__ float g_peT[Hsz * Psz];     // transposed product embeds [h][p]
__device__ float g_degs[Psz];
__device__ float g_agg[Psz * Hsz];     // (tf32-rounded in reduce)
__device__ float g_trans[Psz * Hsz];
__device__ float g_cat[Bsz * 512];     // [hidden | rounded enriched]
__device__ float g_gatep[Bsz * Hsz];   // gate preactivation
__device__ float g_wr[983040];         // rounded weights
__device__ float g_adjr[Psz * Psz];    // rounded adj
__device__ float g_part[4 * PH];       // split-K partials for adj GEMM

// per-group barrier counters (16 groups; monotonic, separate cache lines)
__device__ unsigned g_grp_cnt[16 * 32];

__device__ __forceinline__ float sigmoidf_(float x) { return 1.0f / (1.0f + expf(-x)); }

// single-MUFU tanh (PTX tanh.approx.f32, sm_75+; target-independent)
__device__ __forceinline__ float tanh_fast(float x) {
    float r;
    asm("tanh.approx.f32 %0, %1;" : "=f"(r) : "f"(x));
    return r;
}
// sigmoid via tanh: sigma(x) = 0.5*tanh(x/2) + 0.5  (one MUFU instead of exp+div)
__device__ __forceinline__ float sig_fast(float x) {
    return fmaf(0.5f, tanh_fast(0.5f * x), 0.5f);
}

// ---------------- helpers (target-independent PTX) ----------------
__device__ __forceinline__ uint32_t f2tf32(float f) {
    uint32_t r;
    asm("cvt.rna.tf32.f32 %0, %1;" : "=r"(r) : "f"(f));
    return r;
}
__device__ __forceinline__ float rnd_tf32(float f) { return __uint_as_float(f2tf32(f)); }
__device__ __forceinline__ void mma_m16n8k8(float d[4], const uint32_t a[4], const uint32_t b[2]) {
    asm volatile(
        "mma.sync.aligned.m16n8k8.row.col.f32.tf32.tf32.f32 "
        "{%0,%1,%2,%3}, {%4,%5,%6,%7}, {%8,%9}, {%0,%1,%2,%3};"
        : "+f"(d[0]), "+f"(d[1]), "+f"(d[2]), "+f"(d[3])
        : "r"(a[0]), "r"(a[1]), "r"(a[2]), "r"(a[3]), "r"(b[0]), "r"(b[1]));
}
__device__ __forceinline__ uint32_t smem_u32(const void* p) {
    uint32_t a;
    asm("{ .reg .u64 t; cvta.to.shared.u64 t, %1; cvt.u32.u64 %0, t; }" : "=r"(a) : "l"(p));
    return a;
}
__device__ __forceinline__ void ldsm_x4(uint32_t r[4], uint32_t addr) {
    asm volatile("ldmatrix.sync.aligned.m8n8.x4.shared.b16 {%0,%1,%2,%3}, [%4];"
                 : "=r"(r[0]), "=r"(r[1]), "=r"(r[2]), "=r"(r[3]) : "r"(addr));
}
__device__ __forceinline__ void ldsm_x2(uint32_t r[2], uint32_t addr) {
    asm volatile("ldmatrix.sync.aligned.m8n8.x2.shared.b16 {%0,%1}, [%2];"
                 : "=r"(r[0]), "=r"(r[1]) : "r"(addr));
}
__device__ __forceinline__ void cp_async16(uint32_t dst, const void* src) {
    asm volatile("cp.async.cg.shared.global [%0], [%1], 16;" :: "r"(dst), "l"(src));
}
__device__ __forceinline__ void cp_commit() {
    asm volatile("cp.async.commit_group;" ::: "memory");
}
template<int N> __device__ __forceinline__ void cp_wait() {
    asm volatile("cp.async.wait_group %0;" :: "n"(N) : "memory");
}

// ---------------- round_all: fused RNE rounding of all 7 weight blobs ----------------
__global__ __launch_bounds__(256) void round_all(
    const float* __restrict__ s0, const float* __restrict__ s1,
    const float* __restrict__ s2, const float* __restrict__ s3,
    const float* __restrict__ s4, const float* __restrict__ s5,
    const float* __restrict__ s6, float* __restrict__ dst)
{
    int i = blockIdx.x * 256 + threadIdx.x;
    if (i >= 245760) return;
    const float* src; int off;
    if      (i < 65536)  { src = s0; off = 0; }
    else if (i < 131072) { src = s1; off = 65536; }
    else if (i < 163840) { src = s2; off = 131072; }
    else if (i < 180224) { src = s3; off = 163840; }
    else if (i < 196608) { src = s4; off = 180224; }
    else if (i < 212992) { src = s5; off = 196608; }
    else                 { src = s6; off = 212992; }
    float4 v = ((const float4*)src)[i - off];
    v.x = rnd_tf32(v.x); v.y = rnd_tf32(v.y); v.z = rnd_tf32(v.z); v.w = rnd_tf32(v.w);
    ((float4*)dst)[i] = v;
}

// ================= persistent LSTM layer (R13 structure; tanh.approx epilogue) =================
__global__ __launch_bounds__(256) void lstm_persist(
    const float* __restrict__ xp, float* __restrict__ hseq,
    const float* __restrict__ Whh)
{
    extern __shared__ char sbuf[];
    uint32_t (*As)[260] = (uint32_t(*)[260])sbuf;
    uint32_t (*Bs)[260] = (uint32_t(*)[260])(sbuf + 66560);
    float (*Cs)[132]    = (float(*)[132])sbuf;   // aliases As

    const int tid = threadIdx.x;
    const int wid = tid >> 5, lane = tid & 31;
    const int wr = wid & 1, wc = wid >> 1;
    const int grp = blockIdx.x >> 3;
    const int m0 = grp * 64;
    const int j0 = (blockIdx.x & 7) * 32;
    unsigned* cntP = &g_grp_cnt[grp * 32];

    const uint32_t asBase = smem_u32(&As[0][0]);
    const uint32_t bsBase = smem_u32(&Bs[0][0]);

    for (int i = tid; i < 128 * 64; i += 256) {
        int r = i >> 6, cc = (i & 63) << 2;
        int wrow = (r >> 5) * 256 + j0 + (r & 31);
        float4 v = *(const float4*)&Whh[(size_t)wrow * 256 + cc];
        uint32_t* p = &Bs[r][cc];
        p[0] = f2tf32(v.x); p[1] = f2tf32(v.y); p[2] = f2tf32(v.z); p[3] = f2tf32(v.w);
    }

    const int lg = lane >> 3, lr8 = lane & 7;
    uint32_t aAddr[2], bAddr[4];
    #pragma unroll
    for (int mi = 0; mi < 2; mi++)
        aAddr[mi] = asBase + (uint32_t)(wr * 32 + mi * 16 + lr8 + (lg & 1) * 8) * 1040u
                    + (uint32_t)((lg >> 1) * 4) * 4u;
    #pragma unroll
    for (int ni = 0; ni < 4; ni++)
        bAddr[ni] = bsBase + (uint32_t)(wc * 32 + ni * 8 + lr8) * 1040u
                    + (uint32_t)((lg & 1) * 4) * 4u;

    const int srow = tid >> 2, sc0 = tid & 3;
    const uint32_t sdst0 = asBase + (uint32_t)srow * 1040u;

    const int bl = tid >> 2, jl0 = (tid & 3) * 8;
    const int b = m0 + bl;
    float creg[8];
    unsigned base = 0;

    // ---- t = 0 ----
    {
        const float* xb = &xp[((size_t)b * Tsz + 0) * 1024 + j0 + jl0];
        float xi[8], xg[8], xo[8], hn[8];
        *(float4*)&xi[0] = *(const float4*)&xb[0];    *(float4*)&xi[4] = *(const float4*)&xb[4];
        *(float4*)&xg[0] = *(const float4*)&xb[512];  *(float4*)&xg[4] = *(const float4*)&xb[516];
        *(float4*)&xo[0] = *(const float4*)&xb[768];  *(float4*)&xo[4] = *(const float4*)&xb[772];
        #pragma unroll
        for (int e = 0; e < 8; e++) {
            creg[e] = sig_fast(xi[e]) * tanh_fast(xg[e]);
            hn[e] = rnd_tf32(sig_fast(xo[e]) * tanh_fast(creg[e]));
        }
        float* hb = &hseq[((size_t)b * Tsz + 0) * 256 + j0 + jl0];
        *(float4*)&hb[0] = *(float4*)&hn[0];  *(float4*)&hb[4] = *(float4*)&hn[4];
    }
    __syncthreads();
    if (tid == 0) {
        unsigned arr;
        asm volatile("atom.release.gpu.add.u32 %0, [%1], 1;" : "=r"(arr) : "l"(cntP) : "memory");
        base = arr & ~7u;
    }

    for (int t = 1; t < Tsz; t++) {
        // prefetch xp (overlaps inter-CTA wait)
        const float* xb = &xp[((size_t)b * Tsz + t) * 1024 + j0 + jl0];
        float xi[8], xf[8], xg[8], xo[8];
        *(float4*)&xi[0] = *(const float4*)&xb[0];    *(float4*)&xi[4] = *(const float4*)&xb[4];
        *(float4*)&xf[0] = *(const float4*)&xb[256];  *(float4*)&xf[4] = *(const float4*)&xb[260];
        *(float4*)&xg[0] = *(const float4*)&xb[512];  *(float4*)&xg[4] = *(const float4*)&xb[516];
        *(float4*)&xo[0] = *(const float4*)&xb[768];  *(float4*)&xo[4] = *(const float4*)&xb[772];

        if (tid == 0) {
            unsigned target = base + 8u * (unsigned)t;
            unsigned c;
            do {
                asm volatile("ld.acquire.gpu.u32 %0, [%1];" : "=r"(c) : "l"(cntP) : "memory");
            } while ((int)(c - target) < 0);
        }
        __syncthreads();

        {
            const float* srcrow = &hseq[((size_t)(m0 + srow) * Tsz + (t - 1)) * 256];
            #pragma unroll
            for (int u = 0; u < 8; u++) {
                int cf4 = sc0 + u * 4;
                cp_async16(sdst0 + (uint32_t)cf4 * 16u, srcrow + cf4 * 4);
            }
            cp_commit();
            #pragma unroll
            for (int u = 8; u < 16; u++) {
                int cf4 = sc0 + u * 4;
                cp_async16(sdst0 + (uint32_t)cf4 * 16u, srcrow + cf4 * 4);
            }
            cp_commit();
        }

        float d[2][4][4] = {};
        cp_wait<1>();
        __syncthreads();
        #pragma unroll 8
        for (int k8 = 0; k8 < 16; k8++) {
            const uint32_t off = (uint32_t)k8 * 32u;
            uint32_t a[2][4], bfr[4][2];
            #pragma unroll
            for (int mi = 0; mi < 2; mi++) ldsm_x4(a[mi], aAddr[mi] + off);
            #pragma unroll
            for (int ni = 0; ni < 4; ni++) ldsm_x2(bfr[ni], bAddr[ni] + off);
            #pragma unroll
            for (int mi = 0; mi < 2; mi++)
                #pragma unroll
                for (int ni = 0; ni < 4; ni++)
                    mma_m16n8k8(d[mi][ni], a[mi], bfr[ni]);
        }
        cp_wait<0>();
        __syncthreads();
        #pragma unroll 8
        for (int k8 = 16; k8 < 32; k8++) {
            const uint32_t off = (uint32_t)k8 * 32u;
            uint32_t a[2][4], bfr[4][2];
            #pragma unroll
            for (int mi = 0; mi < 2; mi++) ldsm_x4(a[mi], aAddr[mi] + off);
            #pragma unroll
            for (int ni = 0; ni < 4; ni++) ldsm_x2(bfr[ni], bAddr[ni] + off);
            #pragma unroll
            for (int mi = 0; mi < 2; mi++)
                #pragma unroll
                for (int ni = 0; ni < 4; ni++)
                    mma_m16n8k8(d[mi][ni], a[mi], bfr[ni]);
        }
        __syncthreads();

        const int gID = lane >> 2, tig = lane & 3;
        #pragma unroll
        for (int mi = 0; mi < 2; mi++) {
            int m = wr * 32 + mi * 16 + gID;
            #pragma unroll
            for (int ni = 0; ni < 4; ni++) {
                int n = wc * 32 + ni * 8 + tig * 2;
                *(float2*)&Cs[m][n]     = make_float2(d[mi][ni][0], d[mi][ni][1]);
                *(float2*)&Cs[m + 8][n] = make_float2(d[mi][ni][2], d[mi][ni][3]);
            }
        }
        __syncthreads();

        float hn[8];
        #pragma unroll
        for (int e = 0; e < 8; e++) {
            int jl = jl0 + e;
            float gi = Cs[bl][jl]      + xi[e];
            float gf = Cs[bl][32 + jl] + xf[e];
            float gg = Cs[bl][64 + jl] + xg[e];
            float go = Cs[bl][96 + jl] + xo[e];
            creg[e] = sig_fast(gf) * creg[e] + sig_fast(gi) * tanh_fast(gg);
            hn[e] = rnd_tf32(sig_fast(go) * tanh_fast(creg[e]));
        }
        float* hb = &hseq[((size_t)b * Tsz + t) * 256 + j0 + jl0];
        *(float4*)&hb[0] = *(float4*)&hn[0];  *(float4*)&hb[4] = *(float4*)&hn[4];

        __syncthreads();
        if (tid == 0)
            asm volatile("red.release.gpu.add.u32 [%0], 1;" :: "l"(cntP) : "memory");
    }
}

// ================= mm_nt_tf32 v2: cp.async double-buffered, CTA 128x128, split-K =================
__global__ __launch_bounds__(256) void mm_nt_tf32(
    const float* __restrict__ A, const float* __restrict__ W,
    const float* __restrict__ b1, const float* __restrict__ b2,
    const float* __restrict__ rs,
    float* __restrict__ C, int Nall, int lda, int Kchunk, int roundC, size_t partStride)
{
    extern __shared__ char mmbuf[];
    const uint32_t sb = smem_u32(mmbuf);
    const int tid = threadIdx.x;
    const int wid = tid >> 5, lane = tid & 31;
    const int gID = lane >> 2, tig = lane & 3;
    const int wr = wid & 3, wc = wid >> 2;
    const int m0 = blockIdx.y * 128, n0 = blockIdx.x * 128;
    const int kStart = blockIdx.z * Kchunk;
    C += (size_t)blockIdx.z * partStride;

    const int lg = lane >> 3, lr8 = lane & 7;
    uint32_t aOff[2], bOff[4];
    #pragma unroll
    for (int mi = 0; mi < 2; mi++)
        aOff[mi] = (uint32_t)(wr * 32 + mi * 16 + lr8 + (lg & 1) * 8) * 144u
                   + (uint32_t)((lg >> 1) * 4) * 4u;
    #pragma unroll
    for (int ni = 0; ni < 4; ni++)
        bOff[ni] = 18432u + (uint32_t)(wc * 64 + ni * 16 + (lg >> 1) * 8 + lr8) * 144u
                   + (uint32_t)((lg & 1) * 4) * 4u;

    float d[2][8][4] = {};
    const int nk = Kchunk >> 5;

    auto load_stage = [&](int kc, int s) {
        const int k0 = kStart + (kc << 5);
        const uint32_t base = sb + (uint32_t)s * 36864u;
        #pragma unroll
        for (int i = 0; i < 4; i++) {
            int idx = tid + i * 256;
            int r = idx >> 3, c16 = idx & 7;
            cp_async16(base + (uint32_t)r * 144u + (uint32_t)c16 * 16u,
                       &A[(size_t)(m0 + r) * lda + k0 + c16 * 4]);
        }
        #pragma unroll
        for (int i = 0; i < 4; i++) {
            int idx = tid + i * 256;
            int r = idx >> 3, c16 = idx & 7;
            cp_async16(base + 18432u + (uint32_t)r * 144u + (uint32_t)c16 * 16u,
                       &W[(size_t)(n0 + r) * lda + k0 + c16 * 4]);
        }
        cp_commit();
    };

    load_stage(0, 0);
    for (int kc = 0; kc < nk; kc++) {
        const int s = kc & 1;
        const uint32_t stBase = sb + (uint32_t)s * 36864u;
        if (kc + 1 < nk) {
            load_stage(kc + 1, s ^ 1);
            cp_wait<1>();
        } else {
            cp_wait<0>();
        }
        __syncthreads();
        #pragma unroll
        for (int k8 = 0; k8 < 4; k8++) {
            const uint32_t off = stBase + (uint32_t)k8 * 32u;
            uint32_t a[2][4], b[4][4];
            #pragma unroll
            for (int mi = 0; mi < 2; mi++) ldsm_x4(a[mi], off + aOff[mi]);
            #pragma unroll
            for (int ni = 0; ni < 4; ni++) ldsm_x4(b[ni], off + bOff[ni]);
            #pragma unroll
            for (int mi = 0; mi < 2; mi++)
                #pragma unroll
                for (int ni = 0; ni < 4; ni++) {
                    mma_m16n8k8(d[mi][ni * 2],     a[mi], &b[ni][0]);
                    mma_m16n8k8(d[mi][ni * 2 + 1], a[mi], &b[ni][2]);
                }
        }
        __syncthreads();
    }
    #pragma unroll
    for (int mi = 0; mi < 2; mi++) {
        int m = m0 + wr * 32 + mi * 16 + gID;
        float s0 = rs ? rs[m] : 1.0f;
        float s1 = rs ? rs[m + 8] : 1.0f;
        #pragma unroll
        for (int ni = 0; ni < 8; ni++) {
            int n = n0 + wc * 64 + ni * 8 + tig * 2;
            float bb0 = 0.f, bb1 = 0.f;
            if (b1) { bb0 += b1[n]; bb1 += b1[n + 1]; }
            if (b2) { bb0 += b2[n]; bb1 += b2[n + 1]; }
            float v00 = d[mi][ni][0] * s0 + bb0;
            float v01 = d[mi][ni][1] * s0 + bb1;
            float v10 = d[mi][ni][2] * s1 + bb0;
            float v11 = d[mi][ni][3] * s1 + bb1;
            if (roundC) { v00 = rnd_tf32(v00); v01 = rnd_tf32(v01);
                          v10 = rnd_tf32(v10); v11 = rnd_tf32(v11); }
            C[(size_t)m * Nall + n]           = v00;
            C[(size_t)m * Nall + n + 1]       = v01;
            C[(size_t)(m + 8) * Nall + n]     = v10;
            C[(size_t)(m + 8) * Nall + n + 1] = v11;
        }
    }
}

// ---------------- reduce split-K partials -> agg ----------------
__global__ __launch_bounds__(256) void agg_reduce(
    const float* __restrict__ part, const float* __restrict__ degscale,
    float* __restrict__ agg)
{
    int p = blockIdx.x, h = threadIdx.x;
    size_t i = (size_t)p * Hsz + h;
    float s = part[i] + part[i + PH] + part[i + 2 * (size_t)PH] + part[i + 3 * (size_t)PH];
    agg[i] = rnd_tf32(s * degscale[p]);
}

// ---------------- VSN: one warp per (b,t); outputs tf32-rounded ----------------
__global__ __launch_bounds__(256) void vsn_kernel(
    const float* __restrict__ x,
    const float* __restrict__ emb_w, const float* __restrict__ emb_b,
    const float* __restrict__ sel_w, const float* __restrict__ sel_b,
    float* __restrict__ h)
{
    const int lane = threadIdx.x & 31;
    const size_t bt = (size_t)blockIdx.x * 8 + (threadIdx.x >> 5);
    float xv = (lane < Fsz) ? x[bt * Fsz + lane] : 0.f;
    float xs[Fsz];
    #pragma unroll
    for (int f = 0; f < Fsz; f++) xs[f] = __shfl_sync(0xffffffffu, xv, f);
    float lg = -1e30f;
    if (lane < Fsz) {
        lg = sel_b[lane];
        #pragma unroll
        for (int j = 0; j < Fsz; j++) lg += xs[j] * sel_w[lane * Fsz + j];
    }
    float mx = lg;
    #pragma unroll
    for (int off = 16; off; off >>= 1) mx = fmaxf(mx, __shfl_xor_sync(0xffffffffu, mx, off));
    float ex = (lane < Fsz) ? expf(lg - mx) : 0.f;
    float den = ex;
    #pragma unroll
    for (int off = 16; off; off >>= 1) den += __shfl_xor_sync(0xffffffffu, den, off);
    float wv = ex / den;
    float wf[Fsz];
    #pragma unroll
    for (int f = 0; f < Fsz; f++) wf[f] = __shfl_sync(0xffffffffu, wv, f);

    const int o0 = lane * 8;
    float acc[8] = {};
    #pragma unroll
    for (int f = 0; f < Fsz; f++) {
        float4 w0 = *(const float4*)&emb_w[f * Hsz + o0];
        float4 w1 = *(const float4*)&emb_w[f * Hsz + o0 + 4];
        float4 c0 = *(const float4*)&emb_b[f * Hsz + o0];
        float4 c1 = *(const float4*)&emb_b[f * Hsz + o0 + 4];
        float wfx = wf[f], xf = xs[f];
        acc[0] += wfx * (xf * w0.x + c0.x); acc[1] += wfx * (xf * w0.y + c0.y);
        acc[2] += wfx * (xf * w0.z + c0.z); acc[3] += wfx * (xf * w0.w + c0.w);
        acc[4] += wfx * (xf * w1.x + c1.x); acc[5] += wfx * (xf * w1.y + c1.y);
        acc[6] += wfx * (xf * w1.z + c1.z); acc[7] += wfx * (xf * w1.w + c1.w);
    }
    #pragma unroll
    for (int e = 0; e < 8; e++) acc[e] = rnd_tf32(acc[e]);
    float* hb = &h[bt * Hsz + o0];
    *(float4*)&hb[0] = *(float4*)&acc[0];
    *(float4*)&hb[4] = *(float4*)&acc[4];
}

// ---------------- gather h_last ----------------
__global__ __launch_bounds__(256) void qgather_kernel(
    const float* __restrict__ h, float* __restrict__ qg)
{
    int b = blockIdx.x, tid = threadIdx.x;
    qg[(size_t)b * Hsz + tid] = h[((size_t)b * Tsz + (Tsz - 1)) * Hsz + tid];
}

// ---------------- attention (last query only); v-sum parallel over 128 threads ----------------
__global__ __launch_bounds__(128) void attn_last_kernel(
    const float* __restrict__ q, const float* __restrict__ kv,
    float* __restrict__ o)
{
    int b = blockIdx.x, hd = blockIdx.y;
    int tid = threadIdx.x;
    __shared__ float qs[DHEAD];
    __shared__ float sc[Tsz];
    __shared__ float red[Tsz];
    if (tid < DHEAD) qs[tid] = q[(size_t)b * Hsz + hd * DHEAD + tid];
    __syncthreads();
    const float* kp = &kv[((size_t)b * Tsz + tid) * 512 + hd * DHEAD];
    float s = 0.f;
#pragma unroll 8
    for (int d = 0; d < DHEAD; d++) s += qs[d] * kp[d];
    s *= 0.125f;
    sc[tid] = s;
    red[tid] = s;
    __syncthreads();
    for (int off = 64; off; off >>= 1) {
        if (tid < off) red[tid] = fmaxf(red[tid], red[tid + off]);
        __syncthreads();
    }
    float mx = red[0];
    __syncthreads();
    float e = expf(sc[tid] - mx);
    sc[tid] = e;
    red[tid] = e;
    __syncthreads();
    for (int off = 64; off; off >>= 1) {
        if (tid < off) red[tid] += red[tid + off];
        __syncthreads();
    }
    float inv = 1.0f / red[0];
    __syncthreads();
    sc[tid] *= inv;
    __syncthreads();
    {
        int dd = tid & 63, hf = tid >> 6;
        float acc = 0.f;
        const float* vbase = &kv[((size_t)b * Tsz + hf * 64) * 512 + 256 + hd * DHEAD + dd];
        #pragma unroll 8
        for (int t = 0; t < 64; t++)
            acc += sc[hf * 64 + t] * vbase[(size_t)t * 512];
        red[tid] = acc;
        __syncthreads();
        if (tid < 64)
            o[(size_t)b * Hsz + hd * DHEAD + tid] = rnd_tf32(red[tid] + red[tid + 64]);
    }
}

// ---------------- GNN helpers ----------------
__global__ __launch_bounds__(256) void scatterT_kernel(
    const float* __restrict__ hidden, const int* __restrict__ sku,
    float* __restrict__ peT)
{
    int b = blockIdx.x, tid = threadIdx.x;
    peT[(size_t)tid * Psz + sku[b]] = hidden[(size_t)b * Hsz + tid];
}

// fused: degree sum + tf32-round adj row
__global__ __launch_bounds__(256) void deg_round_kernel(
    const float* __restrict__ adj, float* __restrict__ adjr, float* __restrict__ scale)
{
    int p = blockIdx.x, tid = threadIdx.x;
    float s = 0.f;
    const float* row = &adj[(size_t)p * Psz];
    float* rowr = &adjr[(size_t)p * Psz];
    #pragma unroll
    for (int u = 0; u < 2; u++) {
        int f4 = tid + u * 256;
        float4 v = *(const float4*)&row[f4 * 4];
        s += v.x + v.y + v.z + v.w;
        v.x = rnd_tf32(v.x); v.y = rnd_tf32(v.y); v.z = rnd_tf32(v.z); v.w = rnd_tf32(v.w);
        *(float4*)&rowr[f4 * 4] = v;
    }
    __shared__ float red[256];
    red[tid] = s; __syncthreads();
    for (int off = 128; off; off >>= 1) {
        if (tid < off) red[tid] += red[tid + off];
        __syncthreads();
    }
    if (tid == 0) scale[p] = 1.0f / fmaxf(red[0], 1e-6f);
}

__global__ __launch_bounds__(256) void geluln_kernel(
    float* __restrict__ x, const float* __restrict__ g,
    const float* __restrict__ b)
{
    int p = blockIdx.x, tid = threadIdx.x;
    float v = x[(size_t)p * Hsz + tid];
    float ge = 0.5f * v * (1.0f + erff(v * 0.70710678118654752f));
    __shared__ float red[256];
    red[tid] = ge; __syncthreads();
    for (int off = 128; off; off >>= 1) {
        if (tid < off) red[tid] += red[tid + off];
        __syncthreads();
    }
    float mu = red[0] * (1.0f / Hsz);
    __syncthreads();
    float d = ge - mu;
    red[tid] = d * d; __syncthreads();
    for (int off = 128; off; off >>= 1) {
        if (tid < off) red[tid] += red[tid + off];
        __syncthreads();
    }
    float var = red[0] * (1.0f / Hsz);
    x[(size_t)p * Hsz + tid] = d * rsqrtf(var + 1e-5f) * g[tid] + b[tid];
}

// ---------------- cat build: [hidden | rnd(enriched)] ----------------
__global__ __launch_bounds__(256) void cat_kernel(
    const float* __restrict__ hidden, const float* __restrict__ trans,
    const int* __restrict__ sku, float* __restrict__ cat)
{
    int b = blockIdx.x, tid = threadIdx.x;
    cat[(size_t)b * 512 + tid] = hidden[(size_t)b * Hsz + tid];
    cat[(size_t)b * 512 + 256 + tid] = rnd_tf32(trans[(size_t)sku[b] * Hsz + tid]);
}

// ---------------- final epilogue ----------------
__global__ __launch_bounds__(256) void final_epi_kernel(
    const float* __restrict__ gatep, const float* __restrict__ hidden,
    const float* __restrict__ trans, const int* __restrict__ sku,
    const float* __restrict__ out_w, const float* __restrict__ out_b,
    float* __restrict__ out)
{
    int b = blockIdx.x, tid = threadIdx.x;
    float gt = sigmoidf_(gatep[(size_t)b * Hsz + tid]);
    float enr = trans[(size_t)sku[b] * Hsz + tid];
    float hid = hidden[(size_t)b * Hsz + tid];
    float comb = gt * enr + (1.0f - gt) * hid;
    __shared__ float red[256];
    red[tid] = comb * out_w[tid];
    __syncthreads();
    for (int off = 128; off; off >>= 1) {
        if (tid < off) red[tid] += red[tid + off];
        __syncthreads();
    }
    if (tid == 0) out[b] = red[0] + out_b[0];
}

// ---------------- launch ----------------
#define LSTM_SMEM 199680
#define MM_SMEM 73728
// g_wr offsets (floats)
#define WR_WIH0 0
#define WR_WIH1 262144
#define WR_KV   524288
#define WR_AO   655360
#define WR_GNN  720896
#define WR_Q    786432
#define WR_GATE 851968

extern "C" void kernel_launch(void* const* d_in, const int* in_sizes, int n_in,
                              void* d_out, int out_size)
{
    const float* x          = (const float*)d_in[0];
    const int*   sku        = (const int*)  d_in[1];
    const float* adj        = (const float*)d_in[2];
    const float* vsn_emb_w  = (const float*)d_in[3];
    const float* vsn_emb_b  = (const float*)d_in[4];
    const float* vsn_sel_w  = (const float*)d_in[5];
    const float* vsn_sel_b  = (const float*)d_in[6];
    const float* Wih0       = (const float*)d_in[7];
    const float* Whh0       = (const float*)d_in[8];
    const float* bih0       = (const float*)d_in[9];
    const float* bhh0       = (const float*)d_in[10];
    const float* Wih1       = (const float*)d_in[11];
    const float* Whh1       = (const float*)d_in[12];
    const float* bih1       = (const float*)d_in[13];
    const float* bhh1       = (const float*)d_in[14];
    const float* attn_in_w  = (const float*)d_in[15];
    const float* attn_in_b  = (const float*)d_in[16];
    const float* attn_out_w = (const float*)d_in[17];
    const float* attn_out_b = (const float*)d_in[18];
    const float* gnn_w      = (const float*)d_in[19];
    const float* gnn_b      = (const float*)d_in[20];
    const float* ln_g       = (const float*)d_in[21];
    const float* ln_b       = (const float*)d_in[22];
    const float* gate_w     = (const float*)d_in[23];
    const float* gate_b     = (const float*)d_in[24];
    const float* out_w      = (const float*)d_in[25];
    const float* out_b      = (const float*)d_in[26];
    float* out = (float*)d_out;

    static float *hP = nullptr, *xpP, *qP, *qgP, *oP, *hidP, *peTP, *degP, *aggP, *transP,
                 *catP, *gpP, *wrP, *adjrP, *partP;
    if (!hP) {
        cudaGetSymbolAddress((void**)&hP, g_h);
        cudaGetSymbolAddress((void**)&xpP, g_xp);
        cudaGetSymbolAddress((void**)&qP, g_q);
        cudaGetSymbolAddress((void**)&qgP, g_qg);
        cudaGetSymbolAddress((void**)&oP, g_o);
        cudaGetSymbolAddress((void**)&hidP, g_hidden);
        cudaGetSymbolAddress((void**)&degP, g_degs);
        cudaGetSymbolAddress((void**)&peTP, g_peT);
        cudaGetSymbolAddress((void**)&aggP, g_agg);
        cudaGetSymbolAddress((void**)&transP, g_trans);
        cudaGetSymbolAddress((void**)&catP, g_cat);
        cudaGetSymbolAddress((void**)&gpP, g_gatep);
        cudaGetSymbolAddress((void**)&wrP, g_wr);
        cudaGetSymbolAddress((void**)&adjrP, g_adjr);
        cudaGetSymbolAddress((void**)&partP, g_part);
        cudaFuncSetAttribute(lstm_persist, cudaFuncAttributeMaxDynamicSharedMemorySize, LSTM_SMEM);
        cudaFuncSetAttribute(mm_nt_tf32, cudaFuncAttributeMaxDynamicSharedMemorySize, MM_SMEM);
    }

    // weight pre-rounding (one fused launch) + VSN
    round_all<<<960, 256>>>(Wih0, Wih1, attn_in_w + (size_t)Hsz*Hsz, attn_out_w,
                            gnn_w, attn_in_w, gate_w, wrP);
    vsn_kernel<<<BT / 8, 256>>>(x, vsn_emb_w, vsn_emb_b, vsn_sel_w, vsn_sel_b, hP);

    // LSTM layer 0
    mm_nt_tf32<<<dim3(8, BT / 128), 256, MM_SMEM>>>(hP, wrP + WR_WIH0, bih0, bhh0, nullptr,
                                                    xpP, 1024, 256, 256, 0, 0);
    lstm_persist<<<NCTA, 256, LSTM_SMEM>>>(xpP, hP, Whh0);

    // LSTM layer 1
    mm_nt_tf32<<<dim3(8, BT / 128), 256, MM_SMEM>>>(hP, wrP + WR_WIH1, bih1, bhh1, nullptr,
                                                    xpP, 1024, 256, 256, 0, 0);
    lstm_persist<<<NCTA, 256, LSTM_SMEM>>>(xpP, hP, Whh1);

    // k,v projection; q via gather + GEMM
    mm_nt_tf32<<<dim3(4, BT / 128), 256, MM_SMEM>>>(hP, wrP + WR_KV, attn_in_b + Hsz, nullptr,
                                                    nullptr, xpP, 512, 256, 256, 0, 0);
    qgather_kernel<<<Bsz, 256>>>(hP, qgP);
    mm_nt_tf32<<<dim3(2, Bsz / 128), 256, MM_SMEM>>>(qgP, wrP + WR_Q, attn_in_b, nullptr,
                                                     nullptr, qP, 256, 256, 256, 0, 0);

    // attention at last query (o tf32-rounded)
    attn_last_kernel<<<dim3(Bsz, NHEADS), 128>>>(qP, xpP, oP);

    // output projection (hidden tf32-rounded)
    mm_nt_tf32<<<dim3(2, Bsz / 128), 256, MM_SMEM>>>(oP, wrP + WR_AO, attn_out_b, nullptr,
                                                     nullptr, hidP, 256, 256, 256, 1, 0);

    // GNN
    cudaMemsetAsync(peTP, 0, (size_t)Hsz * Psz * sizeof(float));
    scatterT_kernel<<<Bsz, 256>>>(hidP, sku, peTP);
    deg_round_kernel<<<Psz, 256>>>(adj, adjrP, degP);
    mm_nt_tf32<<<dim3(2, Psz / 128, 4), 256, MM_SMEM>>>(adjrP, peTP, nullptr, nullptr, nullptr,
                                                        partP, 256, 2048, 512, 0, (size_t)PH);
    agg_reduce<<<Psz, 256>>>(partP, degP, aggP);
    mm_nt_tf32<<<dim3(2, Psz / 128), 256, MM_SMEM>>>(aggP, wrP + WR_GNN, gnn_b, nullptr,
                                                     nullptr, transP, 256, 256, 256, 0, 0);
    geluln_kernel<<<Psz, 256>>>(transP, ln_g, ln_b);

    // gate via GEMM + epilogue
    cat_kernel<<<Bsz, 256>>>(hidP, transP, sku, catP);
    mm_nt_tf32<<<dim3(2, Bsz / 128), 256, MM_SMEM>>>(catP, wrP + WR_GATE, gate_b, nullptr,
                                                     nullptr, gpP, 256, 512, 512, 0, 0);
    final_epi_kernel<<<Bsz, 256>>>(gpP, hidP, transP, sku, out_w, out_b, out);
}